// round 11
// baseline (speedup 1.0000x reference)
#include <cuda_runtime.h>
#include <cuda_bf16.h>
#include <math.h>
#include <stdint.h>

#define BB 2
#define SS 4096
#define DD 768
#define NH 12
#define HD 64
#define WIN 256
#define BH (BB*NH)

// ---------------------------------------------------------------------------
// scratch (bf16 hi/lo everywhere)
// ---------------------------------------------------------------------------
__device__ __nv_bfloat16 g_ahi[BB*SS*DD];
__device__ __nv_bfloat16 g_alo[BB*SS*DD];
__device__ __nv_bfloat16 g_wthi[3][DD*DD];
__device__ __nv_bfloat16 g_wtlo[3][DD*DD];
__device__ __nv_bfloat16 g_qhi[BH*SS*HD], g_qlo[BH*SS*HD];
__device__ __nv_bfloat16 g_khi[BH*SS*HD], g_klo[BH*SS*HD];
__device__ __nv_bfloat16 g_vthi[BH*HD*SS], g_vtlo[BH*HD*SS];

// ---------------------------------------------------------------------------
// helpers
// ---------------------------------------------------------------------------
__device__ __forceinline__ uint32_t smem_u32(const void* p) {
    uint32_t a;
    asm("{ .reg .u64 t; cvta.to.shared.u64 t, %1; cvt.u32.u64 %0, t; }"
        : "=r"(a) : "l"(p));
    return a;
}
#define LDSM4(r0,r1,r2,r3,addr) \
    asm volatile("ldmatrix.sync.aligned.m8n8.x4.shared.b16 {%0,%1,%2,%3}, [%4];" \
        : "=r"(r0),"=r"(r1),"=r"(r2),"=r"(r3) : "r"(addr))
#define MMA16816(c, a, b0, b1) \
    asm volatile("mma.sync.aligned.m16n8k16.row.col.f32.bf16.bf16.f32 " \
        "{%0,%1,%2,%3}, {%4,%5,%6,%7}, {%8,%9}, {%0,%1,%2,%3};" \
        : "+f"((c)[0]),"+f"((c)[1]),"+f"((c)[2]),"+f"((c)[3]) \
        : "r"((a)[0]),"r"((a)[1]),"r"((a)[2]),"r"((a)[3]),"r"(b0),"r"(b1))
__device__ __forceinline__ void cpa16(uint32_t dst, const void* src) {
    asm volatile("cp.async.cg.shared.global [%0], [%1], 16;"
                 :: "r"(dst), "l"(src));
}
#define CPA_COMMIT() asm volatile("cp.async.commit_group;" ::: "memory")
#define CPA_WAIT(n)  asm volatile("cp.async.wait_group %0;" :: "n"(n) : "memory")

// pack two f32 -> bf16x2 (first operand -> high half)
__device__ __forceinline__ uint32_t cvt_bf2(float hi, float lo) {
    uint32_t r;
    asm("cvt.rn.bf16x2.f32 %0, %1, %2;" : "=r"(r) : "f"(hi), "f"(lo));
    return r;
}
__device__ __forceinline__ float bf2_lo(uint32_t u) {
    return __uint_as_float(u << 16);
}
__device__ __forceinline__ float bf2_hi(uint32_t u) {
    return __uint_as_float(u & 0xFFFF0000u);
}

__device__ __forceinline__ float expfast(float x) {
    float z = x * 1.4426950408889634f;
    z = fmaxf(z, -126.0f);
    float t = z + 12582912.0f;
    int   ni = __float_as_int(t) - 0x4B400000;
    float n = t - 12582912.0f;
    float r = z - n;
    float p = fmaf(1.5403530393381609e-4f, r, 1.3333558146428443e-3f);
    p = fmaf(p, r, 9.6181291076284772e-3f);
    p = fmaf(p, r, 5.5504108664821580e-2f);
    p = fmaf(p, r, 2.4022650695910072e-1f);
    p = fmaf(p, r, 6.9314718055994531e-1f);
    p = fmaf(p, r, 1.0f);
    return p * __int_as_float((ni + 127) << 23);
}

// ---------------------------------------------------------------------------
// prep: split hidden / weights into bf16 hi/lo
// ---------------------------------------------------------------------------
__global__ __launch_bounds__(256) void asplit(const float4* __restrict__ in,
                                              __nv_bfloat162* __restrict__ hi,
                                              __nv_bfloat162* __restrict__ lo,
                                              int n4)
{
    int i = blockIdx.x * blockDim.x + threadIdx.x;
    int stride = gridDim.x * blockDim.x;
    for (; i < n4; i += stride) {
        float4 f = in[i];
        __nv_bfloat16 hx = __float2bfloat16(f.x);
        __nv_bfloat16 hy = __float2bfloat16(f.y);
        __nv_bfloat16 hz = __float2bfloat16(f.z);
        __nv_bfloat16 hw = __float2bfloat16(f.w);
        hi[2*i]   = __nv_bfloat162(hx, hy);
        hi[2*i+1] = __nv_bfloat162(hz, hw);
        lo[2*i]   = __nv_bfloat162(__float2bfloat16(f.x - __bfloat162float(hx)),
                                   __float2bfloat16(f.y - __bfloat162float(hy)));
        lo[2*i+1] = __nv_bfloat162(__float2bfloat16(f.z - __bfloat162float(hz)),
                                   __float2bfloat16(f.w - __bfloat162float(hw)));
    }
}

// transpose + split all three W [K,N] fp32 -> Wt hi/lo [N,K] bf16 (z selects)
__global__ __launch_bounds__(256) void wsplit3(
    const float* __restrict__ Wq, const float* __restrict__ Wk,
    const float* __restrict__ Wv,
    __nv_bfloat16* __restrict__ hi_all, __nv_bfloat16* __restrict__ lo_all)
{
    __shared__ float t[32][33];
    const int z = blockIdx.z;
    const float* __restrict__ W = (z == 0) ? Wq : ((z == 1) ? Wk : Wv);
    __nv_bfloat16* hi = hi_all + (size_t)z * DD * DD;
    __nv_bfloat16* lo = lo_all + (size_t)z * DD * DD;
    int tx = threadIdx.x, ty = threadIdx.y;
    int bx = blockIdx.x * 32, by = blockIdx.y * 32;
    #pragma unroll
    for (int i = 0; i < 4; i++)
        t[ty + i*8][tx] = W[(size_t)(by + ty + i*8) * DD + bx + tx];
    __syncthreads();
    #pragma unroll
    for (int i = 0; i < 4; i++) {
        float x = t[tx][ty + i*8];
        __nv_bfloat16 h = __float2bfloat16(x);
        hi[(size_t)(bx + ty + i*8) * DD + by + tx] = h;
        lo[(size_t)(bx + ty + i*8) * DD + by + tx] =
            __float2bfloat16(x - __bfloat162float(h));
    }
}

// ---------------------------------------------------------------------------
// QKV GEMM on tensor cores; z=0/1 -> Q/K hi/lo [s][d]; z=2 -> VT hi/lo [d][s]
// ---------------------------------------------------------------------------
#define TSTR    40
#define TILE_E  (128 * TSTR)
#define STAGE_E (4 * TILE_E)
#define G_SMEM  (2 * STAGE_E * 2)
#define NCHUNK  (DD / 32)

__global__ __launch_bounds__(256) void qkv_gemm_mma(
    const __nv_bfloat16* __restrict__ Ahi, const __nv_bfloat16* __restrict__ Alo,
    const __nv_bfloat16* __restrict__ Whi_all,
    const __nv_bfloat16* __restrict__ Wlo_all,
    const float* __restrict__ bq, const float* __restrict__ bk,
    const float* __restrict__ bv,
    __nv_bfloat16* __restrict__ qh, __nv_bfloat16* __restrict__ ql,
    __nv_bfloat16* __restrict__ kh, __nv_bfloat16* __restrict__ kl,
    __nv_bfloat16* __restrict__ vth, __nv_bfloat16* __restrict__ vtl)
{
    extern __shared__ __nv_bfloat16 gsm[];
    const uint32_t smb = smem_u32(gsm);

    const int z = blockIdx.z;
    const __nv_bfloat16* __restrict__ Whi = Whi_all + (size_t)z * DD * DD;
    const __nv_bfloat16* __restrict__ Wlo = Wlo_all + (size_t)z * DD * DD;
    const float* __restrict__ bias = (z == 0) ? bq : ((z == 1) ? bk : bv);
    const float scale = (z == 0) ? 0.125f : 1.0f;

    const int tid  = threadIdx.x;
    const int wid  = tid >> 5;
    const int lane = tid & 31;
    const int bm   = blockIdx.y * 128;
    const int bn   = blockIdx.x * 128;
    const int mrow0 = (wid & 3) * 32;
    const int ncol0 = (wid >> 2) * 64;
    const int lr0 = tid >> 2;
    const int lg  = tid & 3;

    float acc[2][8][4];
    #pragma unroll
    for (int i = 0; i < 2; i++)
        #pragma unroll
        for (int j = 0; j < 8; j++)
            #pragma unroll
            for (int u = 0; u < 4; u++) acc[i][j][u] = 0.f;

    const int lm  = lane >> 3;
    const int lr8 = lane & 7;
    const int a_row_off = (lm & 1) * 8 + lr8;
    const int a_col_off = (lm >> 1) * 8;
    const int b_row_off = (lm >> 1) * 8 + lr8;
    const int b_col_off = (lm & 1) * 8;

    auto load_chunk = [&](int c, int s) {
        const int k0 = c * 32;
        const uint32_t sbase = smb + (uint32_t)(s * STAGE_E) * 2;
        const __nv_bfloat16* srcs[4] = {
            Ahi + (size_t)bm * DD + k0, Alo + (size_t)bm * DD + k0,
            Whi + (size_t)bn * DD + k0, Wlo + (size_t)bn * DD + k0 };
        #pragma unroll
        for (int t4 = 0; t4 < 4; t4++) {
            #pragma unroll
            for (int it = 0; it < 2; it++) {
                int r = lr0 + it * 64;
                cpa16(sbase + (uint32_t)(t4 * TILE_E + r * TSTR + lg * 8) * 2,
                      srcs[t4] + (size_t)r * DD + lg * 8);
            }
        }
        CPA_COMMIT();
    };

    load_chunk(0, 0);
    CPA_WAIT(0);
    __syncthreads();

    for (int c = 0; c < NCHUNK; c++) {
        if (c + 1 < NCHUNK) {
            load_chunk(c + 1, (c + 1) & 1);
            CPA_WAIT(1);
        } else {
            CPA_WAIT(0);
        }
        __syncthreads();

        const uint32_t sbase = smb + (uint32_t)((c & 1) * STAGE_E) * 2;
        const uint32_t baseAhi = sbase;
        const uint32_t baseAlo = sbase + (uint32_t)TILE_E * 2;
        const uint32_t baseWhi = sbase + (uint32_t)(2 * TILE_E) * 2;
        const uint32_t baseWlo = sbase + (uint32_t)(3 * TILE_E) * 2;

        #pragma unroll
        for (int kk = 0; kk < 32; kk += 16) {
            uint32_t ah[2][4], al[2][4];
            #pragma unroll
            for (int mt2 = 0; mt2 < 2; mt2++) {
                uint32_t off = (uint32_t)((mrow0 + mt2 * 16 + a_row_off) * TSTR
                                          + kk + a_col_off) * 2;
                LDSM4(ah[mt2][0], ah[mt2][1], ah[mt2][2], ah[mt2][3],
                      baseAhi + off);
                LDSM4(al[mt2][0], al[mt2][1], al[mt2][2], al[mt2][3],
                      baseAlo + off);
            }
            uint32_t bh[16], bl[16];
            #pragma unroll
            for (int ng = 0; ng < 4; ng++) {
                uint32_t off = (uint32_t)((ncol0 + ng * 16 + b_row_off) * TSTR
                                          + kk + b_col_off) * 2;
                LDSM4(bh[ng*4+0], bh[ng*4+1], bh[ng*4+2], bh[ng*4+3],
                      baseWhi + off);
                LDSM4(bl[ng*4+0], bl[ng*4+1], bl[ng*4+2], bl[ng*4+3],
                      baseWlo + off);
            }
            #pragma unroll
            for (int mt2 = 0; mt2 < 2; mt2++) {
                #pragma unroll
                for (int nt = 0; nt < 8; nt++) {
                    int bi = (nt >> 1) * 4 + (nt & 1) * 2;
                    MMA16816(acc[mt2][nt], ah[mt2], bh[bi], bh[bi+1]);
                    MMA16816(acc[mt2][nt], ah[mt2], bl[bi], bl[bi+1]);
                    MMA16816(acc[mt2][nt], al[mt2], bh[bi], bh[bi+1]);
                }
            }
        }
        __syncthreads();
    }

    if (z < 2) {
        // Q/K epilogue: (acc+bias)*scale -> bf16 hi/lo pairs at [b,h,s,d]
        __nv_bfloat16* dh = (z == 0) ? qh : kh;
        __nv_bfloat16* dl = (z == 0) ? ql : kl;
        #pragma unroll
        for (int mt2 = 0; mt2 < 2; mt2++) {
            int grow0 = bm + mrow0 + mt2 * 16 + (lane >> 2);
            int b0 = grow0 >> 12;
            int s0 = grow0 & (SS - 1);
            #pragma unroll
            for (int nt = 0; nt < 8; nt++) {
                int gcol = bn + ncol0 + nt * 8 + 2 * (lane & 3);
                int head = gcol >> 6;
                int d    = gcol & 63;
                float2 bsv = *(const float2*)(bias + gcol);
                size_t idx = ((size_t)(b0 * NH + head) * SS + s0) * HD + d;
                float v0 = (acc[mt2][nt][0] + bsv.x) * scale;
                float v1 = (acc[mt2][nt][1] + bsv.y) * scale;
                float v2 = (acc[mt2][nt][2] + bsv.x) * scale;
                float v3 = (acc[mt2][nt][3] + bsv.y) * scale;
                uint32_t h01 = cvt_bf2(v1, v0);
                uint32_t l01 = cvt_bf2(v1 - bf2_hi(h01), v0 - bf2_lo(h01));
                uint32_t h23 = cvt_bf2(v3, v2);
                uint32_t l23 = cvt_bf2(v3 - bf2_hi(h23), v2 - bf2_lo(h23));
                *(uint32_t*)(dh + idx) = h01;
                *(uint32_t*)(dl + idx) = l01;
                *(uint32_t*)(dh + idx + (size_t)8 * HD) = h23;
                *(uint32_t*)(dl + idx + (size_t)8 * HD) = l23;
            }
        }
    } else {
        // V epilogue: stage bf16 hi/lo in smem, write transposed VT [d][s]
        unsigned short* sh = (unsigned short*)gsm;       // [128][136]
        unsigned short* sl = sh + 128 * 136;
        #pragma unroll
        for (int mt2 = 0; mt2 < 2; mt2++) {
            int r0 = mrow0 + mt2 * 16 + (lane >> 2);
            #pragma unroll
            for (int nt = 0; nt < 8; nt++) {
                int c = ncol0 + nt * 8 + 2 * (lane & 3);
                float2 bsv = *(const float2*)(bias + bn + c);
                float v0 = acc[mt2][nt][0] + bsv.x;
                float v1 = acc[mt2][nt][1] + bsv.y;
                float v2 = acc[mt2][nt][2] + bsv.x;
                float v3 = acc[mt2][nt][3] + bsv.y;
                uint32_t h01 = cvt_bf2(v1, v0);
                uint32_t l01 = cvt_bf2(v1 - bf2_hi(h01), v0 - bf2_lo(h01));
                uint32_t h23 = cvt_bf2(v3, v2);
                uint32_t l23 = cvt_bf2(v3 - bf2_hi(h23), v2 - bf2_lo(h23));
                *(uint32_t*)&sh[r0 * 136 + c]       = h01;
                *(uint32_t*)&sl[r0 * 136 + c]       = l01;
                *(uint32_t*)&sh[(r0 + 8) * 136 + c] = h23;
                *(uint32_t*)&sl[(r0 + 8) * 136 + c] = l23;
            }
        }
        __syncthreads();
        const int col  = tid >> 1;
        const int half = tid & 1;
        const int head = (bn + col) >> 6;
        const int d    = col & 63;
        const int b0   = bm >> 12;
        const int s0   = (bm & (SS - 1)) + half * 64;
        __nv_bfloat16* dsth = vth + ((size_t)(b0 * NH + head) * HD + d) * SS + s0;
        __nv_bfloat16* dstl = vtl + ((size_t)(b0 * NH + head) * HD + d) * SS + s0;
        unsigned short wbuf[8];
        #pragma unroll
        for (int blk = 0; blk < 8; blk++) {
            #pragma unroll
            for (int i = 0; i < 8; i++)
                wbuf[i] = sh[(half * 64 + blk * 8 + i) * 136 + col];
            *(uint4*)(dsth + blk * 8) = *(uint4*)wbuf;
        }
        #pragma unroll
        for (int blk = 0; blk < 8; blk++) {
            #pragma unroll
            for (int i = 0; i < 8; i++)
                wbuf[i] = sl[(half * 64 + blk * 8 + i) * 136 + col];
            *(uint4*)(dstl + blk * 8) = *(uint4*)wbuf;
        }
    }
}

// ---------------------------------------------------------------------------
// Banded attention on tensor cores: 128-q tile, double-buffered K/V tiles,
// bf16 hi/lo 3-pass MMAs, FA2 register P conversion, poly exp.
// ---------------------------------------------------------------------------
#define ASTR 72
#define STAGE_BF (4 * 64 * ASTR)                 // bf16 elems per stage
#define A_SMEM   (2 * STAGE_BF * 2)              // bytes (dynamic)

__global__ __launch_bounds__(256, 2) void attn_mma(
    const __nv_bfloat16* __restrict__ qhi, const __nv_bfloat16* __restrict__ qlo,
    const __nv_bfloat16* __restrict__ khi, const __nv_bfloat16* __restrict__ klo,
    const __nv_bfloat16* __restrict__ vthi, const __nv_bfloat16* __restrict__ vtlo,
    const float* __restrict__ fmask, const unsigned char* __restrict__ imask,
    float* __restrict__ out)
{
    extern __shared__ __nv_bfloat16 asmem[];
    __shared__ float fmk[2][64];
    const uint32_t smb = smem_u32(asmem);

    const int tid  = threadIdx.x;
    const int w    = tid >> 5;
    const int lane = tid & 31;
    const int bh   = blockIdx.y;
    const int b    = bh / NH;
    const int hh   = bh % NH;
    const int q0   = blockIdx.x * 128;

    const int lm  = lane >> 3;
    const int lr8 = lane & 7;
    const int a_row_off = (lm & 1) * 8 + lr8;
    const int a_col_off = (lm >> 1) * 8;
    const int b_row_off = (lm >> 1) * 8 + lr8;
    const int b_col_off = (lm & 1) * 8;
    const int gid = lane >> 2;
    const int tig = lane & 3;

    // ---- stage Q into stage-0 region (hi rows 0-127, lo rows 128-255) ----
    #pragma unroll
    for (int it = 0; it < 8; it++) {
        int c = it * 256 + tid;
        int hilo = c >> 10;
        int r    = (c >> 3) & 127;
        int col  = c & 7;
        const __nv_bfloat16* src = (hilo ? qlo : qhi)
            + ((size_t)bh * SS + q0 + r) * HD + col * 8;
        cpa16(smb + (uint32_t)(hilo * 128 * ASTR + r * ASTR + col * 8) * 2, src);
    }
    CPA_COMMIT();
    CPA_WAIT(0);
    __syncthreads();

    uint32_t qfh[16], qfl[16];
    #pragma unroll
    for (int kb = 0; kb < 4; kb++) {
        uint32_t off = (uint32_t)((w * 16 + a_row_off) * ASTR
                                  + kb * 16 + a_col_off) * 2;
        LDSM4(qfh[kb*4+0], qfh[kb*4+1], qfh[kb*4+2], qfh[kb*4+3], smb + off);
        LDSM4(qfl[kb*4+0], qfl[kb*4+1], qfl[kb*4+2], qfl[kb*4+3],
              smb + (uint32_t)(128 * ASTR) * 2 + off);
    }
    __syncthreads();       // Q region about to be reused as stage 0

    float oacc[8][4];
    #pragma unroll
    for (int j = 0; j < 8; j++)
        #pragma unroll
        for (int u = 0; u < 4; u++) oacc[j][u] = 0.f;
    float rsum0 = 0.f, rsum1 = 0.f;

    const int row_lo = q0 + w * 16 + gid;
    const int row_hi = row_lo + 8;

    auto issue_tile = [&](int t, int st) {
        const int kstart = q0 - WIN + t * 64;
        #pragma unroll
        for (int it = 0; it < 8; it++) {
            int c    = it * 256 + tid;
            int tile = c >> 9;
            int r    = (c >> 3) & 63;
            int col  = c & 7;
            const __nv_bfloat16* src;
            if (tile == 0)
                src = khi + ((size_t)bh * SS + kstart + r) * HD + col * 8;
            else if (tile == 1)
                src = klo + ((size_t)bh * SS + kstart + r) * HD + col * 8;
            else if (tile == 2)
                src = vthi + ((size_t)bh * HD + r) * SS + kstart + col * 8;
            else
                src = vtlo + ((size_t)bh * HD + r) * SS + kstart + col * 8;
            cpa16(smb + (uint32_t)(st * STAGE_BF + tile * 64 * ASTR
                                   + r * ASTR + col * 8) * 2, src);
        }
        CPA_COMMIT();
        if (tid < 64) {
            float mv = fmask[b * SS + kstart + tid];
            fmk[st][tid] = (mv != 0.f) ? -1e30f : 0.f;
        }
    };

    // active tile range (kstart in [0, SS-64], multiples of 64)
    const int tfirst = (q0 < WIN) ? ((WIN - q0) >> 6) : 0;
    int tlast = (SS - 64 + WIN - q0) >> 6;
    if (tlast > 9) tlast = 9;

    issue_tile(tfirst, 0);
    int st = 0;
    for (int t = tfirst; t <= tlast; t++, st ^= 1) {
        if (t < tlast) {
            issue_tile(t + 1, st ^ 1);
            CPA_WAIT(1);
        } else {
            CPA_WAIT(0);
        }
        __syncthreads();

        const int kstart = q0 - WIN + t * 64;
        const bool edge = (t < 2) || (t > 7);
        const uint32_t sb = smb + (uint32_t)(st * STAGE_BF) * 2;

        // ---- S = Q K^T (3-pass hi/lo) ----
        float s[8][4];
        #pragma unroll
        for (int j = 0; j < 8; j++)
            #pragma unroll
            for (int u = 0; u < 4; u++) s[j][u] = 0.f;
        #pragma unroll
        for (int kb = 0; kb < 4; kb++) {
            #pragma unroll
            for (int ng = 0; ng < 4; ng++) {
                uint32_t off = (uint32_t)((ng * 16 + b_row_off) * ASTR
                                          + kb * 16 + b_col_off) * 2;
                uint32_t kh0, kh1, kh2, kh3, kl0, kl1, kl2, kl3;
                LDSM4(kh0, kh1, kh2, kh3, sb + off);
                LDSM4(kl0, kl1, kl2, kl3,
                      sb + (uint32_t)(64 * ASTR) * 2 + off);
                MMA16816(s[2*ng],   &qfh[kb*4], kh0, kh1);
                MMA16816(s[2*ng],   &qfh[kb*4], kl0, kl1);
                MMA16816(s[2*ng],   &qfl[kb*4], kh0, kh1);
                MMA16816(s[2*ng+1], &qfh[kb*4], kh2, kh3);
                MMA16816(s[2*ng+1], &qfh[kb*4], kl2, kl3);
                MMA16816(s[2*ng+1], &qfl[kb*4], kh2, kh3);
            }
        }

        // ---- exp + window mask + row sums ----
        float rl = 0.f, rh = 0.f;
        #pragma unroll
        for (int nf = 0; nf < 8; nf++) {
            int key0 = kstart + nf * 8 + 2 * tig;
            float fm0 = fmk[st][nf * 8 + 2 * tig];
            float fm1 = fmk[st][nf * 8 + 2 * tig + 1];
            float p0 = expfast(s[nf][0] + fm0);
            float p1 = expfast(s[nf][1] + fm1);
            float p2 = expfast(s[nf][2] + fm0);
            float p3 = expfast(s[nf][3] + fm1);
            if (edge) {
                if (abs(key0     - row_lo) > WIN) p0 = 0.f;
                if (abs(key0 + 1 - row_lo) > WIN) p1 = 0.f;
                if (abs(key0     - row_hi) > WIN) p2 = 0.f;
                if (abs(key0 + 1 - row_hi) > WIN) p3 = 0.f;
            }
            s[nf][0] = p0; s[nf][1] = p1; s[nf][2] = p2; s[nf][3] = p3;
            rl += p0 + p1;
            rh += p2 + p3;
        }
        rl += __shfl_xor_sync(0xffffffffu, rl, 1);
        rl += __shfl_xor_sync(0xffffffffu, rl, 2);
        rh += __shfl_xor_sync(0xffffffffu, rh, 1);
        rh += __shfl_xor_sync(0xffffffffu, rh, 2);
        rsum0 += rl;
        rsum1 += rh;

        // ---- P -> bf16 hi/lo A-frags (register-only) ----
        uint32_t aph[4][4], apl[4][4];
        #pragma unroll
        for (int j = 0; j < 4; j++) {
            uint32_t h;
            h = cvt_bf2(s[2*j][1], s[2*j][0]);
            aph[j][0] = h;
            apl[j][0] = cvt_bf2(s[2*j][1] - bf2_hi(h), s[2*j][0] - bf2_lo(h));
            h = cvt_bf2(s[2*j][3], s[2*j][2]);
            aph[j][1] = h;
            apl[j][1] = cvt_bf2(s[2*j][3] - bf2_hi(h), s[2*j][2] - bf2_lo(h));
            h = cvt_bf2(s[2*j+1][1], s[2*j+1][0]);
            aph[j][2] = h;
            apl[j][2] = cvt_bf2(s[2*j+1][1] - bf2_hi(h), s[2*j+1][0] - bf2_lo(h));
            h = cvt_bf2(s[2*j+1][3], s[2*j+1][2]);
            aph[j][3] = h;
            apl[j][3] = cvt_bf2(s[2*j+1][3] - bf2_hi(h), s[2*j+1][2] - bf2_lo(h));
        }

        // ---- O += P V (3-pass hi/lo) ----
        #pragma unroll
        for (int j = 0; j < 4; j++) {
            #pragma unroll
            for (int nb = 0; nb < 4; nb++) {
                uint32_t off = (uint32_t)((nb * 16 + b_row_off) * ASTR
                                          + j * 16 + b_col_off) * 2;
                uint32_t vh0, vh1, vh2, vh3, vl0, vl1, vl2, vl3;
                LDSM4(vh0, vh1, vh2, vh3,
                      sb + (uint32_t)(2 * 64 * ASTR) * 2 + off);
                LDSM4(vl0, vl1, vl2, vl3,
                      sb + (uint32_t)(3 * 64 * ASTR) * 2 + off);
                MMA16816(oacc[2*nb],   aph[j], vh0, vh1);
                MMA16816(oacc[2*nb],   aph[j], vl0, vl1);
                MMA16816(oacc[2*nb],   apl[j], vh0, vh1);
                MMA16816(oacc[2*nb+1], aph[j], vh2, vh3);
                MMA16816(oacc[2*nb+1], aph[j], vl2, vl3);
                MMA16816(oacc[2*nb+1], apl[j], vh2, vh3);
            }
        }
        __syncthreads();
    }

    // ---- epilogue ----
    float inv0 = 1.f / rsum0;
    float inv1 = 1.f / rsum1;
    if (imask[b * SS + row_lo]) inv0 = 0.f;
    if (imask[b * SS + row_hi]) inv1 = 0.f;
    float* o0 = out + ((size_t)b * SS + row_lo) * DD + hh * HD + 2 * tig;
    float* o1 = out + ((size_t)b * SS + row_hi) * DD + hh * HD + 2 * tig;
    #pragma unroll
    for (int nf = 0; nf < 8; nf++) {
        float2 w0 = make_float2(oacc[nf][0] * inv0, oacc[nf][1] * inv0);
        float2 w1 = make_float2(oacc[nf][2] * inv1, oacc[nf][3] * inv1);
        *(float2*)(o0 + nf * 8) = w0;
        *(float2*)(o1 + nf * 8) = w1;
    }
}

// ---------------------------------------------------------------------------
extern "C" void kernel_launch(void* const* d_in, const int* in_sizes, int n_in,
                              void* d_out, int out_size)
{
    const float* hidden = (const float*)d_in[0];
    const float* amask  = (const float*)d_in[1];
    const unsigned char* imask = (const unsigned char*)d_in[2];
    const float* Wq = (const float*)d_in[3];
    const float* bq = (const float*)d_in[4];
    const float* Wk = (const float*)d_in[5];
    const float* bk = (const float*)d_in[6];
    const float* Wv = (const float*)d_in[7];
    const float* bv = (const float*)d_in[8];
    float* out = (float*)d_out;

    __nv_bfloat16 *pahi, *palo, *pwhi, *pwlo;
    __nv_bfloat16 *pqh, *pql, *pkh, *pkl, *pvth, *pvtl;
    cudaGetSymbolAddress((void**)&pahi, g_ahi);
    cudaGetSymbolAddress((void**)&palo, g_alo);
    cudaGetSymbolAddress((void**)&pwhi, g_wthi);
    cudaGetSymbolAddress((void**)&pwlo, g_wtlo);
    cudaGetSymbolAddress((void**)&pqh, g_qhi);
    cudaGetSymbolAddress((void**)&pql, g_qlo);
    cudaGetSymbolAddress((void**)&pkh, g_khi);
    cudaGetSymbolAddress((void**)&pkl, g_klo);
    cudaGetSymbolAddress((void**)&pvth, g_vthi);
    cudaGetSymbolAddress((void**)&pvtl, g_vtlo);

    cudaFuncSetAttribute(qkv_gemm_mma,
                         cudaFuncAttributeMaxDynamicSharedMemorySize, G_SMEM);
    cudaFuncSetAttribute(attn_mma,
                         cudaFuncAttributeMaxDynamicSharedMemorySize, A_SMEM);

    // prep: bf16 hi/lo splits
    asplit<<<592, 256>>>((const float4*)hidden,
                         (__nv_bfloat162*)pahi, (__nv_bfloat162*)palo,
                         BB * SS * DD / 4);
    dim3 wb(32, 8), wg(DD / 32, DD / 32, 3);
    wsplit3<<<wg, wb>>>(Wq, Wk, Wv, pwhi, pwlo);

    // tensor-core QKV GEMMs -> Q/K hi/lo + VT hi/lo
    dim3 gg(DD / 128, (BB * SS) / 128, 3);
    qkv_gemm_mma<<<gg, 256, G_SMEM>>>(pahi, palo, pwhi, pwlo,
                                      bq, bk, bv,
                                      pqh, pql, pkh, pkl, pvth, pvtl);

    // tensor-core banded attention (double-buffered)
    dim3 agrid(SS / 128, BH);
    attn_mma<<<agrid, 256, A_SMEM>>>(pqh, pql, pkh, pkl, pvth, pvtl,
                                     amask, imask, out);
}

// round 13
// speedup vs baseline: 1.0898x; 1.0898x over previous
#include <cuda_runtime.h>
#include <cuda_bf16.h>
#include <math.h>
#include <stdint.h>

#define BB 2
#define SS 4096
#define DD 768
#define NH 12
#define HD 64
#define WIN 256
#define BH (BB*NH)

// ---------------------------------------------------------------------------
// scratch (bf16 hi/lo everywhere)
// ---------------------------------------------------------------------------
__device__ __nv_bfloat16 g_ahi[BB*SS*DD];
__device__ __nv_bfloat16 g_alo[BB*SS*DD];
__device__ __nv_bfloat16 g_wthi[3][DD*DD];
__device__ __nv_bfloat16 g_wtlo[3][DD*DD];
__device__ __nv_bfloat16 g_qhi[BH*SS*HD], g_qlo[BH*SS*HD];
__device__ __nv_bfloat16 g_khi[BH*SS*HD], g_klo[BH*SS*HD];
__device__ __nv_bfloat16 g_vhi[BH*SS*HD], g_vlo[BH*SS*HD];
__device__ __nv_bfloat16 g_vthi[BH*HD*SS], g_vtlo[BH*HD*SS];

// ---------------------------------------------------------------------------
// helpers
// ---------------------------------------------------------------------------
__device__ __forceinline__ uint32_t smem_u32(const void* p) {
    uint32_t a;
    asm("{ .reg .u64 t; cvta.to.shared.u64 t, %1; cvt.u32.u64 %0, t; }"
        : "=r"(a) : "l"(p));
    return a;
}
#define LDSM4(r0,r1,r2,r3,addr) \
    asm volatile("ldmatrix.sync.aligned.m8n8.x4.shared.b16 {%0,%1,%2,%3}, [%4];" \
        : "=r"(r0),"=r"(r1),"=r"(r2),"=r"(r3) : "r"(addr))
#define MMA16816(c, a, b0, b1) \
    asm volatile("mma.sync.aligned.m16n8k16.row.col.f32.bf16.bf16.f32 " \
        "{%0,%1,%2,%3}, {%4,%5,%6,%7}, {%8,%9}, {%0,%1,%2,%3};" \
        : "+f"((c)[0]),"+f"((c)[1]),"+f"((c)[2]),"+f"((c)[3]) \
        : "r"((a)[0]),"r"((a)[1]),"r"((a)[2]),"r"((a)[3]),"r"(b0),"r"(b1))
__device__ __forceinline__ void cpa16(uint32_t dst, const void* src) {
    asm volatile("cp.async.cg.shared.global [%0], [%1], 16;"
                 :: "r"(dst), "l"(src));
}
#define CPA_COMMIT() asm volatile("cp.async.commit_group;" ::: "memory")
#define CPA_WAIT(n)  asm volatile("cp.async.wait_group %0;" :: "n"(n) : "memory")

// pack two f32 -> bf16x2 (first operand -> high half)
__device__ __forceinline__ uint32_t cvt_bf2(float hi, float lo) {
    uint32_t r;
    asm("cvt.rn.bf16x2.f32 %0, %1, %2;" : "=r"(r) : "f"(hi), "f"(lo));
    return r;
}
__device__ __forceinline__ float bf2_lo(uint32_t u) {
    return __uint_as_float(u << 16);
}
__device__ __forceinline__ float bf2_hi(uint32_t u) {
    return __uint_as_float(u & 0xFFFF0000u);
}

__device__ __forceinline__ float expfast(float x) {
    float z = x * 1.4426950408889634f;
    z = fmaxf(z, -126.0f);
    float t = z + 12582912.0f;
    int   ni = __float_as_int(t) - 0x4B400000;
    float n = t - 12582912.0f;
    float r = z - n;
    float p = fmaf(1.5403530393381609e-4f, r, 1.3333558146428443e-3f);
    p = fmaf(p, r, 9.6181291076284772e-3f);
    p = fmaf(p, r, 5.5504108664821580e-2f);
    p = fmaf(p, r, 2.4022650695910072e-1f);
    p = fmaf(p, r, 6.9314718055994531e-1f);
    p = fmaf(p, r, 1.0f);
    return p * __int_as_float((ni + 127) << 23);
}

// ---------------------------------------------------------------------------
// prep kernels
// ---------------------------------------------------------------------------
__global__ __launch_bounds__(256) void asplit(const float4* __restrict__ in,
                                              __nv_bfloat162* __restrict__ hi,
                                              __nv_bfloat162* __restrict__ lo,
                                              int n4)
{
    int i = blockIdx.x * blockDim.x + threadIdx.x;
    int stride = gridDim.x * blockDim.x;
    for (; i < n4; i += stride) {
        float4 f = in[i];
        __nv_bfloat16 hx = __float2bfloat16(f.x);
        __nv_bfloat16 hy = __float2bfloat16(f.y);
        __nv_bfloat16 hz = __float2bfloat16(f.z);
        __nv_bfloat16 hw = __float2bfloat16(f.w);
        hi[2*i]   = __nv_bfloat162(hx, hy);
        hi[2*i+1] = __nv_bfloat162(hz, hw);
        lo[2*i]   = __nv_bfloat162(__float2bfloat16(f.x - __bfloat162float(hx)),
                                   __float2bfloat16(f.y - __bfloat162float(hy)));
        lo[2*i+1] = __nv_bfloat162(__float2bfloat16(f.z - __bfloat162float(hz)),
                                   __float2bfloat16(f.w - __bfloat162float(hw)));
    }
}

__global__ __launch_bounds__(256) void wsplit3(
    const float* __restrict__ Wq, const float* __restrict__ Wk,
    const float* __restrict__ Wv,
    __nv_bfloat16* __restrict__ hi_all, __nv_bfloat16* __restrict__ lo_all)
{
    __shared__ float t[32][33];
    const int z = blockIdx.z;
    const float* __restrict__ W = (z == 0) ? Wq : ((z == 1) ? Wk : Wv);
    __nv_bfloat16* hi = hi_all + (size_t)z * DD * DD;
    __nv_bfloat16* lo = lo_all + (size_t)z * DD * DD;
    int tx = threadIdx.x, ty = threadIdx.y;
    int bx = blockIdx.x * 32, by = blockIdx.y * 32;
    #pragma unroll
    for (int i = 0; i < 4; i++)
        t[ty + i*8][tx] = W[(size_t)(by + ty + i*8) * DD + bx + tx];
    __syncthreads();
    #pragma unroll
    for (int i = 0; i < 4; i++) {
        float x = t[tx][ty + i*8];
        __nv_bfloat16 h = __float2bfloat16(x);
        hi[(size_t)(bx + ty + i*8) * DD + by + tx] = h;
        lo[(size_t)(bx + ty + i*8) * DD + by + tx] =
            __float2bfloat16(x - __bfloat162float(h));
    }
}

// transpose V [bh][S][64] bf16 -> VT [bh][64][S]; z selects hi/lo
__global__ __launch_bounds__(256) void vtrans(
    const __nv_bfloat16* __restrict__ vhi, const __nv_bfloat16* __restrict__ vlo,
    __nv_bfloat16* __restrict__ vthi, __nv_bfloat16* __restrict__ vtlo)
{
    __shared__ unsigned short sm[64][65];
    const int s0 = blockIdx.x * 64;
    const int bh = blockIdx.y;
    const __nv_bfloat16* src = (blockIdx.z ? vlo : vhi) + (size_t)bh * SS * HD;
    __nv_bfloat16* dst       = (blockIdx.z ? vtlo : vthi) + (size_t)bh * HD * SS;
    const int tid = threadIdx.x;
    const int r = tid >> 2, c0 = (tid & 3) * 16;
    {
        uint4 a = *(const uint4*)(src + (size_t)(s0 + r) * HD + c0);
        uint4 b = *(const uint4*)(src + (size_t)(s0 + r) * HD + c0 + 8);
        const unsigned short* pa = (const unsigned short*)&a;
        const unsigned short* pb = (const unsigned short*)&b;
        #pragma unroll
        for (int i = 0; i < 8; i++) { sm[r][c0+i] = pa[i]; sm[r][c0+8+i] = pb[i]; }
    }
    __syncthreads();
    {
        unsigned short w[16];
        #pragma unroll
        for (int i = 0; i < 16; i++) w[i] = sm[c0 + i][r];
        *(uint4*)(dst + (size_t)r * SS + s0 + c0)     = *(uint4*)&w[0];
        *(uint4*)(dst + (size_t)r * SS + s0 + c0 + 8) = *(uint4*)&w[8];
    }
}

// ---------------------------------------------------------------------------
// QKV GEMM on tensor cores (R10-proven epilogue): Q/K/V hi/lo at [b,h,s,d]
// ---------------------------------------------------------------------------
#define TSTR    40
#define TILE_E  (128 * TSTR)
#define STAGE_E (4 * TILE_E)
#define G_SMEM  (2 * STAGE_E * 2)
#define NCHUNK  (DD / 32)

__global__ __launch_bounds__(256) void qkv_gemm_mma(
    const __nv_bfloat16* __restrict__ Ahi, const __nv_bfloat16* __restrict__ Alo,
    const __nv_bfloat16* __restrict__ Whi_all,
    const __nv_bfloat16* __restrict__ Wlo_all,
    const float* __restrict__ bq, const float* __restrict__ bk,
    const float* __restrict__ bv,
    __nv_bfloat16* __restrict__ qh, __nv_bfloat16* __restrict__ ql,
    __nv_bfloat16* __restrict__ kh, __nv_bfloat16* __restrict__ kl,
    __nv_bfloat16* __restrict__ vh, __nv_bfloat16* __restrict__ vl)
{
    extern __shared__ __nv_bfloat16 gsm[];
    const uint32_t smb = smem_u32(gsm);

    const int z = blockIdx.z;
    const __nv_bfloat16* __restrict__ Whi = Whi_all + (size_t)z * DD * DD;
    const __nv_bfloat16* __restrict__ Wlo = Wlo_all + (size_t)z * DD * DD;
    const float* __restrict__ bias = (z == 0) ? bq : ((z == 1) ? bk : bv);
    __nv_bfloat16* dh = (z == 0) ? qh : ((z == 1) ? kh : vh);
    __nv_bfloat16* dl = (z == 0) ? ql : ((z == 1) ? kl : vl);
    const float scale = (z == 0) ? 0.125f : 1.0f;

    const int tid  = threadIdx.x;
    const int wid  = tid >> 5;
    const int lane = tid & 31;
    const int bm   = blockIdx.y * 128;
    const int bn   = blockIdx.x * 128;
    const int mrow0 = (wid & 3) * 32;
    const int ncol0 = (wid >> 2) * 64;
    const int lr0 = tid >> 2;
    const int lg  = tid & 3;

    float acc[2][8][4];
    #pragma unroll
    for (int i = 0; i < 2; i++)
        #pragma unroll
        for (int j = 0; j < 8; j++)
            #pragma unroll
            for (int u = 0; u < 4; u++) acc[i][j][u] = 0.f;

    const int lm  = lane >> 3;
    const int lr8 = lane & 7;
    const int a_row_off = (lm & 1) * 8 + lr8;
    const int a_col_off = (lm >> 1) * 8;
    const int b_row_off = (lm >> 1) * 8 + lr8;
    const int b_col_off = (lm & 1) * 8;

    auto load_chunk = [&](int c, int s) {
        const int k0 = c * 32;
        const uint32_t sbase = smb + (uint32_t)(s * STAGE_E) * 2;
        const __nv_bfloat16* srcs[4] = {
            Ahi + (size_t)bm * DD + k0, Alo + (size_t)bm * DD + k0,
            Whi + (size_t)bn * DD + k0, Wlo + (size_t)bn * DD + k0 };
        #pragma unroll
        for (int t4 = 0; t4 < 4; t4++) {
            #pragma unroll
            for (int it = 0; it < 2; it++) {
                int r = lr0 + it * 64;
                cpa16(sbase + (uint32_t)(t4 * TILE_E + r * TSTR + lg * 8) * 2,
                      srcs[t4] + (size_t)r * DD + lg * 8);
            }
        }
        CPA_COMMIT();
    };

    load_chunk(0, 0);
    CPA_WAIT(0);
    __syncthreads();

    for (int c = 0; c < NCHUNK; c++) {
        if (c + 1 < NCHUNK) {
            load_chunk(c + 1, (c + 1) & 1);
            CPA_WAIT(1);
        } else {
            CPA_WAIT(0);
        }
        __syncthreads();

        const uint32_t sbase = smb + (uint32_t)((c & 1) * STAGE_E) * 2;
        const uint32_t baseAhi = sbase;
        const uint32_t baseAlo = sbase + (uint32_t)TILE_E * 2;
        const uint32_t baseWhi = sbase + (uint32_t)(2 * TILE_E) * 2;
        const uint32_t baseWlo = sbase + (uint32_t)(3 * TILE_E) * 2;

        #pragma unroll
        for (int kk = 0; kk < 32; kk += 16) {
            uint32_t ah[2][4], al[2][4];
            #pragma unroll
            for (int mt2 = 0; mt2 < 2; mt2++) {
                uint32_t off = (uint32_t)((mrow0 + mt2 * 16 + a_row_off) * TSTR
                                          + kk + a_col_off) * 2;
                LDSM4(ah[mt2][0], ah[mt2][1], ah[mt2][2], ah[mt2][3],
                      baseAhi + off);
                LDSM4(al[mt2][0], al[mt2][1], al[mt2][2], al[mt2][3],
                      baseAlo + off);
            }
            uint32_t bh[16], bl[16];
            #pragma unroll
            for (int ng = 0; ng < 4; ng++) {
                uint32_t off = (uint32_t)((ncol0 + ng * 16 + b_row_off) * TSTR
                                          + kk + b_col_off) * 2;
                LDSM4(bh[ng*4+0], bh[ng*4+1], bh[ng*4+2], bh[ng*4+3],
                      baseWhi + off);
                LDSM4(bl[ng*4+0], bl[ng*4+1], bl[ng*4+2], bl[ng*4+3],
                      baseWlo + off);
            }
            #pragma unroll
            for (int mt2 = 0; mt2 < 2; mt2++) {
                #pragma unroll
                for (int nt = 0; nt < 8; nt++) {
                    int bi = (nt >> 1) * 4 + (nt & 1) * 2;
                    MMA16816(acc[mt2][nt], ah[mt2], bh[bi], bh[bi+1]);
                    MMA16816(acc[mt2][nt], ah[mt2], bl[bi], bl[bi+1]);
                    MMA16816(acc[mt2][nt], al[mt2], bh[bi], bh[bi+1]);
                }
            }
        }
        __syncthreads();
    }

    // epilogue: (acc+bias)*scale -> bf16 hi/lo pairs at [b,h,s,d]
    #pragma unroll
    for (int mt2 = 0; mt2 < 2; mt2++) {
        int grow0 = bm + mrow0 + mt2 * 16 + (lane >> 2);
        int b0 = grow0 >> 12;
        int s0 = grow0 & (SS - 1);
        #pragma unroll
        for (int nt = 0; nt < 8; nt++) {
            int gcol = bn + ncol0 + nt * 8 + 2 * (lane & 3);
            int head = gcol >> 6;
            int d    = gcol & 63;
            float2 bsv = *(const float2*)(bias + gcol);
            size_t idx = ((size_t)(b0 * NH + head) * SS + s0) * HD + d;
            float v0 = (acc[mt2][nt][0] + bsv.x) * scale;
            float v1 = (acc[mt2][nt][1] + bsv.y) * scale;
            float v2 = (acc[mt2][nt][2] + bsv.x) * scale;
            float v3 = (acc[mt2][nt][3] + bsv.y) * scale;
            uint32_t h01 = cvt_bf2(v1, v0);
            uint32_t l01 = cvt_bf2(v1 - bf2_hi(h01), v0 - bf2_lo(h01));
            uint32_t h23 = cvt_bf2(v3, v2);
            uint32_t l23 = cvt_bf2(v3 - bf2_hi(h23), v2 - bf2_lo(h23));
            *(uint32_t*)(dh + idx) = h01;
            *(uint32_t*)(dl + idx) = l01;
            *(uint32_t*)(dh + idx + (size_t)8 * HD) = h23;
            *(uint32_t*)(dl + idx + (size_t)8 * HD) = l23;
        }
    }
}

// ---------------------------------------------------------------------------
// Banded attention on tensor cores (R11-proven): 128-q tile, double-buffered
// K/V tiles, bf16 hi/lo 3-pass MMAs, FA2 register P conversion, poly exp.
// ---------------------------------------------------------------------------
#define ASTR 72
#define STAGE_BF (4 * 64 * ASTR)
#define A_SMEM   (2 * STAGE_BF * 2)

__global__ __launch_bounds__(256, 2) void attn_mma(
    const __nv_bfloat16* __restrict__ qhi, const __nv_bfloat16* __restrict__ qlo,
    const __nv_bfloat16* __restrict__ khi, const __nv_bfloat16* __restrict__ klo,
    const __nv_bfloat16* __restrict__ vthi, const __nv_bfloat16* __restrict__ vtlo,
    const float* __restrict__ fmask, const unsigned char* __restrict__ imask,
    float* __restrict__ out)
{
    extern __shared__ __nv_bfloat16 asmem[];
    __shared__ float fmk[2][64];
    const uint32_t smb = smem_u32(asmem);

    const int tid  = threadIdx.x;
    const int w    = tid >> 5;
    const int lane = tid & 31;
    const int bh   = blockIdx.y;
    const int b    = bh / NH;
    const int hh   = bh % NH;
    const int q0   = blockIdx.x * 128;

    const int lm  = lane >> 3;
    const int lr8 = lane & 7;
    const int a_row_off = (lm & 1) * 8 + lr8;
    const int a_col_off = (lm >> 1) * 8;
    const int b_row_off = (lm >> 1) * 8 + lr8;
    const int b_col_off = (lm & 1) * 8;
    const int gid = lane >> 2;
    const int tig = lane & 3;

    // ---- stage Q (hi rows 0-127, lo rows 128-255) ----
    #pragma unroll
    for (int it = 0; it < 8; it++) {
        int c = it * 256 + tid;
        int hilo = c >> 10;
        int r    = (c >> 3) & 127;
        int col  = c & 7;
        const __nv_bfloat16* src = (hilo ? qlo : qhi)
            + ((size_t)bh * SS + q0 + r) * HD + col * 8;
        cpa16(smb + (uint32_t)(hilo * 128 * ASTR + r * ASTR + col * 8) * 2, src);
    }
    CPA_COMMIT();
    CPA_WAIT(0);
    __syncthreads();

    uint32_t qfh[16], qfl[16];
    #pragma unroll
    for (int kb = 0; kb < 4; kb++) {
        uint32_t off = (uint32_t)((w * 16 + a_row_off) * ASTR
                                  + kb * 16 + a_col_off) * 2;
        LDSM4(qfh[kb*4+0], qfh[kb*4+1], qfh[kb*4+2], qfh[kb*4+3], smb + off);
        LDSM4(qfl[kb*4+0], qfl[kb*4+1], qfl[kb*4+2], qfl[kb*4+3],
              smb + (uint32_t)(128 * ASTR) * 2 + off);
    }
    __syncthreads();

    float oacc[8][4];
    #pragma unroll
    for (int j = 0; j < 8; j++)
        #pragma unroll
        for (int u = 0; u < 4; u++) oacc[j][u] = 0.f;
    float rsum0 = 0.f, rsum1 = 0.f;

    const int row_lo = q0 + w * 16 + gid;
    const int row_hi = row_lo + 8;

    auto issue_tile = [&](int t, int st) {
        const int kstart = q0 - WIN + t * 64;
        #pragma unroll
        for (int it = 0; it < 8; it++) {
            int c    = it * 256 + tid;
            int tile = c >> 9;
            int r    = (c >> 3) & 63;
            int col  = c & 7;
            const __nv_bfloat16* src;
            if (tile == 0)
                src = khi + ((size_t)bh * SS + kstart + r) * HD + col * 8;
            else if (tile == 1)
                src = klo + ((size_t)bh * SS + kstart + r) * HD + col * 8;
            else if (tile == 2)
                src = vthi + ((size_t)bh * HD + r) * SS + kstart + col * 8;
            else
                src = vtlo + ((size_t)bh * HD + r) * SS + kstart + col * 8;
            cpa16(smb + (uint32_t)(st * STAGE_BF + tile * 64 * ASTR
                                   + r * ASTR + col * 8) * 2, src);
        }
        CPA_COMMIT();
        if (tid < 64) {
            float mv = fmask[b * SS + kstart + tid];
            fmk[st][tid] = (mv != 0.f) ? -1e30f : 0.f;
        }
    };

    const int tfirst = (q0 < WIN) ? ((WIN - q0) >> 6) : 0;
    int tlast = (SS - 64 + WIN - q0) >> 6;
    if (tlast > 9) tlast = 9;

    issue_tile(tfirst, 0);
    int st = 0;
    for (int t = tfirst; t <= tlast; t++, st ^= 1) {
        if (t < tlast) {
            issue_tile(t + 1, st ^ 1);
            CPA_WAIT(1);
        } else {
            CPA_WAIT(0);
        }
        __syncthreads();

        const int kstart = q0 - WIN + t * 64;
        const bool edge = (t < 2) || (t > 7);
        const uint32_t sb = smb + (uint32_t)(st * STAGE_BF) * 2;

        // ---- S = Q K^T (3-pass hi/lo) ----
        float s[8][4];
        #pragma unroll
        for (int j = 0; j < 8; j++)
            #pragma unroll
            for (int u = 0; u < 4; u++) s[j][u] = 0.f;
        #pragma unroll
        for (int kb = 0; kb < 4; kb++) {
            #pragma unroll
            for (int ng = 0; ng < 4; ng++) {
                uint32_t off = (uint32_t)((ng * 16 + b_row_off) * ASTR
                                          + kb * 16 + b_col_off) * 2;
                uint32_t kh0, kh1, kh2, kh3, kl0, kl1, kl2, kl3;
                LDSM4(kh0, kh1, kh2, kh3, sb + off);
                LDSM4(kl0, kl1, kl2, kl3,
                      sb + (uint32_t)(64 * ASTR) * 2 + off);
                MMA16816(s[2*ng],   &qfh[kb*4], kh0, kh1);
                MMA16816(s[2*ng],   &qfh[kb*4], kl0, kl1);
                MMA16816(s[2*ng],   &qfl[kb*4], kh0, kh1);
                MMA16816(s[2*ng+1], &qfh[kb*4], kh2, kh3);
                MMA16816(s[2*ng+1], &qfh[kb*4], kl2, kl3);
                MMA16816(s[2*ng+1], &qfl[kb*4], kh2, kh3);
            }
        }

        // ---- exp + window mask + row sums ----
        float rl = 0.f, rh = 0.f;
        #pragma unroll
        for (int nf = 0; nf < 8; nf++) {
            int key0 = kstart + nf * 8 + 2 * tig;
            float fm0 = fmk[st][nf * 8 + 2 * tig];
            float fm1 = fmk[st][nf * 8 + 2 * tig + 1];
            float p0 = expfast(s[nf][0] + fm0);
            float p1 = expfast(s[nf][1] + fm1);
            float p2 = expfast(s[nf][2] + fm0);
            float p3 = expfast(s[nf][3] + fm1);
            if (edge) {
                if (abs(key0     - row_lo) > WIN) p0 = 0.f;
                if (abs(key0 + 1 - row_lo) > WIN) p1 = 0.f;
                if (abs(key0     - row_hi) > WIN) p2 = 0.f;
                if (abs(key0 + 1 - row_hi) > WIN) p3 = 0.f;
            }
            s[nf][0] = p0; s[nf][1] = p1; s[nf][2] = p2; s[nf][3] = p3;
            rl += p0 + p1;
            rh += p2 + p3;
        }
        rl += __shfl_xor_sync(0xffffffffu, rl, 1);
        rl += __shfl_xor_sync(0xffffffffu, rl, 2);
        rh += __shfl_xor_sync(0xffffffffu, rh, 1);
        rh += __shfl_xor_sync(0xffffffffu, rh, 2);
        rsum0 += rl;
        rsum1 += rh;

        // ---- P -> bf16 hi/lo A-frags (register-only) ----
        uint32_t aph[4][4], apl[4][4];
        #pragma unroll
        for (int j = 0; j < 4; j++) {
            uint32_t h;
            h = cvt_bf2(s[2*j][1], s[2*j][0]);
            aph[j][0] = h;
            apl[j][0] = cvt_bf2(s[2*j][1] - bf2_hi(h), s[2*j][0] - bf2_lo(h));
            h = cvt_bf2(s[2*j][3], s[2*j][2]);
            aph[j][1] = h;
            apl[j][1] = cvt_bf2(s[2*j][3] - bf2_hi(h), s[2*j][2] - bf2_lo(h));
            h = cvt_bf2(s[2*j+1][1], s[2*j+1][0]);
            aph[j][2] = h;
            apl[j][2] = cvt_bf2(s[2*j+1][1] - bf2_hi(h), s[2*j+1][0] - bf2_lo(h));
            h = cvt_bf2(s[2*j+1][3], s[2*j+1][2]);
            aph[j][3] = h;
            apl[j][3] = cvt_bf2(s[2*j+1][3] - bf2_hi(h), s[2*j+1][2] - bf2_lo(h));
        }

        // ---- O += P V (3-pass hi/lo) ----
        #pragma unroll
        for (int j = 0; j < 4; j++) {
            #pragma unroll
            for (int nb = 0; nb < 4; nb++) {
                uint32_t off = (uint32_t)((nb * 16 + b_row_off) * ASTR
                                          + j * 16 + b_col_off) * 2;
                uint32_t vh0, vh1, vh2, vh3, vl0, vl1, vl2, vl3;
                LDSM4(vh0, vh1, vh2, vh3,
                      sb + (uint32_t)(2 * 64 * ASTR) * 2 + off);
                LDSM4(vl0, vl1, vl2, vl3,
                      sb + (uint32_t)(3 * 64 * ASTR) * 2 + off);
                MMA16816(oacc[2*nb],   aph[j], vh0, vh1);
                MMA16816(oacc[2*nb],   aph[j], vl0, vl1);
                MMA16816(oacc[2*nb],   apl[j], vh0, vh1);
                MMA16816(oacc[2*nb+1], aph[j], vh2, vh3);
                MMA16816(oacc[2*nb+1], aph[j], vl2, vl3);
                MMA16816(oacc[2*nb+1], apl[j], vh2, vh3);
            }
        }
        __syncthreads();
    }

    // ---- epilogue ----
    float inv0 = 1.f / rsum0;
    float inv1 = 1.f / rsum1;
    if (imask[b * SS + row_lo]) inv0 = 0.f;
    if (imask[b * SS + row_hi]) inv1 = 0.f;
    float* o0 = out + ((size_t)b * SS + row_lo) * DD + hh * HD + 2 * tig;
    float* o1 = out + ((size_t)b * SS + row_hi) * DD + hh * HD + 2 * tig;
    #pragma unroll
    for (int nf = 0; nf < 8; nf++) {
        float2 w0 = make_float2(oacc[nf][0] * inv0, oacc[nf][1] * inv0);
        float2 w1 = make_float2(oacc[nf][2] * inv1, oacc[nf][3] * inv1);
        *(float2*)(o0 + nf * 8) = w0;
        *(float2*)(o1 + nf * 8) = w1;
    }
}

// ---------------------------------------------------------------------------
extern "C" void kernel_launch(void* const* d_in, const int* in_sizes, int n_in,
                              void* d_out, int out_size)
{
    const float* hidden = (const float*)d_in[0];
    const float* amask  = (const float*)d_in[1];
    const unsigned char* imask = (const unsigned char*)d_in[2];
    const float* Wq = (const float*)d_in[3];
    const float* bq = (const float*)d_in[4];
    const float* Wk = (const float*)d_in[5];
    const float* bk = (const float*)d_in[6];
    const float* Wv = (const float*)d_in[7];
    const float* bv = (const float*)d_in[8];
    float* out = (float*)d_out;

    __nv_bfloat16 *pahi, *palo, *pwhi, *pwlo;
    __nv_bfloat16 *pqh, *pql, *pkh, *pkl, *pvh, *pvl, *pvth, *pvtl;
    cudaGetSymbolAddress((void**)&pahi, g_ahi);
    cudaGetSymbolAddress((void**)&palo, g_alo);
    cudaGetSymbolAddress((void**)&pwhi, g_wthi);
    cudaGetSymbolAddress((void**)&pwlo, g_wtlo);
    cudaGetSymbolAddress((void**)&pqh, g_qhi);
    cudaGetSymbolAddress((void**)&pql, g_qlo);
    cudaGetSymbolAddress((void**)&pkh, g_khi);
    cudaGetSymbolAddress((void**)&pkl, g_klo);
    cudaGetSymbolAddress((void**)&pvh, g_vhi);
    cudaGetSymbolAddress((void**)&pvl, g_vlo);
    cudaGetSymbolAddress((void**)&pvth, g_vthi);
    cudaGetSymbolAddress((void**)&pvtl, g_vtlo);

    cudaFuncSetAttribute(qkv_gemm_mma,
                         cudaFuncAttributeMaxDynamicSharedMemorySize, G_SMEM);
    cudaFuncSetAttribute(attn_mma,
                         cudaFuncAttributeMaxDynamicSharedMemorySize, A_SMEM);

    // prep: bf16 hi/lo splits
    asplit<<<592, 256>>>((const float4*)hidden,
                         (__nv_bfloat162*)pahi, (__nv_bfloat162*)palo,
                         BB * SS * DD / 4);
    dim3 wb(32, 8), wg(DD / 32, DD / 32, 3);
    wsplit3<<<wg, wb>>>(Wq, Wk, Wv, pwhi, pwlo);

    // tensor-core QKV GEMMs -> Q/K/V hi/lo
    dim3 gg(DD / 128, (BB * SS) / 128, 3);
    qkv_gemm_mma<<<gg, 256, G_SMEM>>>(pahi, palo, pwhi, pwlo,
                                      bq, bk, bv,
                                      pqh, pql, pkh, pkl, pvh, pvl);

    // V transpose for PV mma B-operand
    dim3 vg(SS / 64, BH, 2);
    vtrans<<<vg, 256>>>(pvh, pvl, pvth, pvtl);

    // tensor-core banded attention (double-buffered)
    dim3 agrid(SS / 128, BH);
    attn_mma<<<agrid, 256, A_SMEM>>>(pqh, pql, pkh, pkl, pvth, pvtl,
                                     amask, imask, out);
}

// round 14
// speedup vs baseline: 1.2772x; 1.1721x over previous
#include <cuda_runtime.h>
#include <cuda_fp16.h>
#include <math.h>
#include <stdint.h>

#define BB 2
#define SS 4096
#define DD 768
#define NH 12
#define HD 64
#define WIN 256
#define BH (BB*NH)

// ---------------------------------------------------------------------------
// scratch (fp16; A single, W hi/lo, Q/K hi/lo, VT hi/lo)
// ---------------------------------------------------------------------------
__device__ __half g_a[BB*SS*DD];
__device__ __half g_wthi[3][DD*DD];
__device__ __half g_wtlo[3][DD*DD];
__device__ __half g_qhi[BH*SS*HD], g_qlo[BH*SS*HD];
__device__ __half g_khi[BH*SS*HD], g_klo[BH*SS*HD];
__device__ __half g_vhi[BH*SS*HD], g_vlo[BH*SS*HD];
__device__ __half g_vthi[BH*HD*SS], g_vtlo[BH*HD*SS];

// ---------------------------------------------------------------------------
// helpers
// ---------------------------------------------------------------------------
__device__ __forceinline__ uint32_t smem_u32(const void* p) {
    uint32_t a;
    asm("{ .reg .u64 t; cvta.to.shared.u64 t, %1; cvt.u32.u64 %0, t; }"
        : "=r"(a) : "l"(p));
    return a;
}
#define LDSM4(r0,r1,r2,r3,addr) \
    asm volatile("ldmatrix.sync.aligned.m8n8.x4.shared.b16 {%0,%1,%2,%3}, [%4];" \
        : "=r"(r0),"=r"(r1),"=r"(r2),"=r"(r3) : "r"(addr))
#define MMA16816(c, a, b0, b1) \
    asm volatile("mma.sync.aligned.m16n8k16.row.col.f32.f16.f16.f32 " \
        "{%0,%1,%2,%3}, {%4,%5,%6,%7}, {%8,%9}, {%0,%1,%2,%3};" \
        : "+f"((c)[0]),"+f"((c)[1]),"+f"((c)[2]),"+f"((c)[3]) \
        : "r"((a)[0]),"r"((a)[1]),"r"((a)[2]),"r"((a)[3]),"r"(b0),"r"(b1))
__device__ __forceinline__ void cpa16(uint32_t dst, const void* src) {
    asm volatile("cp.async.cg.shared.global [%0], [%1], 16;"
                 :: "r"(dst), "l"(src));
}
#define CPA_COMMIT() asm volatile("cp.async.commit_group;" ::: "memory")
#define CPA_WAIT(n)  asm volatile("cp.async.wait_group %0;" :: "n"(n) : "memory")

// pack two f32 -> f16x2 (first operand -> high half)
__device__ __forceinline__ uint32_t cvt_h2(float hi, float lo) {
    uint32_t r;
    asm("cvt.rn.f16x2.f32 %0, %1, %2;" : "=r"(r) : "f"(hi), "f"(lo));
    return r;
}
__device__ __forceinline__ float h2_lo(uint32_t u) {
    float r;
    asm("{.reg .b16 l, h; mov.b32 {l, h}, %1; cvt.f32.f16 %0, l;}"
        : "=f"(r) : "r"(u));
    return r;
}
__device__ __forceinline__ float h2_hi(uint32_t u) {
    float r;
    asm("{.reg .b16 l, h; mov.b32 {l, h}, %1; cvt.f32.f16 %0, h;}"
        : "=f"(r) : "r"(u));
    return r;
}

__device__ __forceinline__ float expfast(float x) {
    float z = x * 1.4426950408889634f;
    z = fmaxf(z, -126.0f);
    float t = z + 12582912.0f;
    int   ni = __float_as_int(t) - 0x4B400000;
    float n = t - 12582912.0f;
    float r = z - n;
    float p = fmaf(1.5403530393381609e-4f, r, 1.3333558146428443e-3f);
    p = fmaf(p, r, 9.6181291076284772e-3f);
    p = fmaf(p, r, 5.5504108664821580e-2f);
    p = fmaf(p, r, 2.4022650695910072e-1f);
    p = fmaf(p, r, 6.9314718055994531e-1f);
    p = fmaf(p, r, 1.0f);
    return p * __int_as_float((ni + 127) << 23);
}

// ---------------------------------------------------------------------------
// prep kernels
// ---------------------------------------------------------------------------
__global__ __launch_bounds__(256) void asplit(const float4* __restrict__ in,
                                              __half2* __restrict__ hi, int n4)
{
    int i = blockIdx.x * blockDim.x + threadIdx.x;
    int stride = gridDim.x * blockDim.x;
    for (; i < n4; i += stride) {
        float4 f = in[i];
        hi[2*i]   = __floats2half2_rn(f.x, f.y);
        hi[2*i+1] = __floats2half2_rn(f.z, f.w);
    }
}

__global__ __launch_bounds__(256) void wsplit3(
    const float* __restrict__ Wq, const float* __restrict__ Wk,
    const float* __restrict__ Wv,
    __half* __restrict__ hi_all, __half* __restrict__ lo_all)
{
    __shared__ float t[32][33];
    const int z = blockIdx.z;
    const float* __restrict__ W = (z == 0) ? Wq : ((z == 1) ? Wk : Wv);
    __half* hi = hi_all + (size_t)z * DD * DD;
    __half* lo = lo_all + (size_t)z * DD * DD;
    int tx = threadIdx.x, ty = threadIdx.y;
    int bx = blockIdx.x * 32, by = blockIdx.y * 32;
    #pragma unroll
    for (int i = 0; i < 4; i++)
        t[ty + i*8][tx] = W[(size_t)(by + ty + i*8) * DD + bx + tx];
    __syncthreads();
    #pragma unroll
    for (int i = 0; i < 4; i++) {
        float x = t[tx][ty + i*8];
        __half h = __float2half_rn(x);
        hi[(size_t)(bx + ty + i*8) * DD + by + tx] = h;
        lo[(size_t)(bx + ty + i*8) * DD + by + tx] =
            __float2half_rn(x - __half2float(h));
    }
}

// transpose V [bh][S][64] -> VT [bh][64][S]; z selects hi/lo
__global__ __launch_bounds__(256) void vtrans(
    const __half* __restrict__ vhi, const __half* __restrict__ vlo,
    __half* __restrict__ vthi, __half* __restrict__ vtlo)
{
    __shared__ unsigned short sm[64][65];
    const int s0 = blockIdx.x * 64;
    const int bh = blockIdx.y;
    const __half* src = (blockIdx.z ? vlo : vhi) + (size_t)bh * SS * HD;
    __half* dst       = (blockIdx.z ? vtlo : vthi) + (size_t)bh * HD * SS;
    const int tid = threadIdx.x;
    const int r = tid >> 2, c0 = (tid & 3) * 16;
    {
        uint4 a = *(const uint4*)(src + (size_t)(s0 + r) * HD + c0);
        uint4 b = *(const uint4*)(src + (size_t)(s0 + r) * HD + c0 + 8);
        const unsigned short* pa = (const unsigned short*)&a;
        const unsigned short* pb = (const unsigned short*)&b;
        #pragma unroll
        for (int i = 0; i < 8; i++) { sm[r][c0+i] = pa[i]; sm[r][c0+8+i] = pb[i]; }
    }
    __syncthreads();
    {
        unsigned short w[16];
        #pragma unroll
        for (int i = 0; i < 16; i++) w[i] = sm[c0 + i][r];
        *(uint4*)(dst + (size_t)r * SS + s0 + c0)     = *(uint4*)&w[0];
        *(uint4*)(dst + (size_t)r * SS + s0 + c0 + 8) = *(uint4*)&w[8];
    }
}

// ---------------------------------------------------------------------------
// QKV GEMM on tensor cores, fp16 2-pass: D = A*(Whi) + A*(Wlo).
// 3 smem tiles per stage (A, Whi, Wlo), double-buffered.
// ---------------------------------------------------------------------------
#define TSTR    40
#define TILE_E  (128 * TSTR)
#define STAGE_E (3 * TILE_E)
#define G_SMEM  (2 * STAGE_E * 2)
#define NCHUNK  (DD / 32)

__global__ __launch_bounds__(256) void qkv_gemm_mma(
    const __half* __restrict__ A,
    const __half* __restrict__ Whi_all, const __half* __restrict__ Wlo_all,
    const float* __restrict__ bq, const float* __restrict__ bk,
    const float* __restrict__ bv,
    __half* __restrict__ qh, __half* __restrict__ ql,
    __half* __restrict__ kh, __half* __restrict__ kl,
    __half* __restrict__ vh, __half* __restrict__ vl)
{
    extern __shared__ __half gsm[];
    const uint32_t smb = smem_u32(gsm);

    const int z = blockIdx.z;
    const __half* __restrict__ Whi = Whi_all + (size_t)z * DD * DD;
    const __half* __restrict__ Wlo = Wlo_all + (size_t)z * DD * DD;
    const float* __restrict__ bias = (z == 0) ? bq : ((z == 1) ? bk : bv);
    __half* dh = (z == 0) ? qh : ((z == 1) ? kh : vh);
    __half* dl = (z == 0) ? ql : ((z == 1) ? kl : vl);
    const float scale = (z == 0) ? 0.125f : 1.0f;

    const int tid  = threadIdx.x;
    const int wid  = tid >> 5;
    const int lane = tid & 31;
    const int bm   = blockIdx.y * 128;
    const int bn   = blockIdx.x * 128;
    const int mrow0 = (wid & 3) * 32;
    const int ncol0 = (wid >> 2) * 64;
    const int lr0 = tid >> 2;
    const int lg  = tid & 3;

    float acc[2][8][4];
    #pragma unroll
    for (int i = 0; i < 2; i++)
        #pragma unroll
        for (int j = 0; j < 8; j++)
            #pragma unroll
            for (int u = 0; u < 4; u++) acc[i][j][u] = 0.f;

    const int lm  = lane >> 3;
    const int lr8 = lane & 7;
    const int a_row_off = (lm & 1) * 8 + lr8;
    const int a_col_off = (lm >> 1) * 8;
    const int b_row_off = (lm >> 1) * 8 + lr8;
    const int b_col_off = (lm & 1) * 8;

    auto load_chunk = [&](int c, int s) {
        const int k0 = c * 32;
        const uint32_t sbase = smb + (uint32_t)(s * STAGE_E) * 2;
        const __half* srcs[3] = {
            A   + (size_t)bm * DD + k0,
            Whi + (size_t)bn * DD + k0,
            Wlo + (size_t)bn * DD + k0 };
        #pragma unroll
        for (int t3 = 0; t3 < 3; t3++) {
            #pragma unroll
            for (int it = 0; it < 2; it++) {
                int r = lr0 + it * 64;
                cpa16(sbase + (uint32_t)(t3 * TILE_E + r * TSTR + lg * 8) * 2,
                      srcs[t3] + (size_t)r * DD + lg * 8);
            }
        }
        CPA_COMMIT();
    };

    load_chunk(0, 0);
    CPA_WAIT(0);
    __syncthreads();

    for (int c = 0; c < NCHUNK; c++) {
        if (c + 1 < NCHUNK) {
            load_chunk(c + 1, (c + 1) & 1);
            CPA_WAIT(1);
        } else {
            CPA_WAIT(0);
        }
        __syncthreads();

        const uint32_t sbase = smb + (uint32_t)((c & 1) * STAGE_E) * 2;
        const uint32_t baseA   = sbase;
        const uint32_t baseWhi = sbase + (uint32_t)TILE_E * 2;
        const uint32_t baseWlo = sbase + (uint32_t)(2 * TILE_E) * 2;

        #pragma unroll
        for (int kk = 0; kk < 32; kk += 16) {
            uint32_t ah[2][4];
            #pragma unroll
            for (int mt2 = 0; mt2 < 2; mt2++) {
                uint32_t off = (uint32_t)((mrow0 + mt2 * 16 + a_row_off) * TSTR
                                          + kk + a_col_off) * 2;
                LDSM4(ah[mt2][0], ah[mt2][1], ah[mt2][2], ah[mt2][3],
                      baseA + off);
            }
            uint32_t bh[16], bl[16];
            #pragma unroll
            for (int ng = 0; ng < 4; ng++) {
                uint32_t off = (uint32_t)((ncol0 + ng * 16 + b_row_off) * TSTR
                                          + kk + b_col_off) * 2;
                LDSM4(bh[ng*4+0], bh[ng*4+1], bh[ng*4+2], bh[ng*4+3],
                      baseWhi + off);
                LDSM4(bl[ng*4+0], bl[ng*4+1], bl[ng*4+2], bl[ng*4+3],
                      baseWlo + off);
            }
            #pragma unroll
            for (int mt2 = 0; mt2 < 2; mt2++) {
                #pragma unroll
                for (int nt = 0; nt < 8; nt++) {
                    int bi = (nt >> 1) * 4 + (nt & 1) * 2;
                    MMA16816(acc[mt2][nt], ah[mt2], bh[bi], bh[bi+1]);
                    MMA16816(acc[mt2][nt], ah[mt2], bl[bi], bl[bi+1]);
                }
            }
        }
        __syncthreads();
    }

    // epilogue: (acc+bias)*scale -> fp16 hi/lo pairs at [b,h,s,d]
    #pragma unroll
    for (int mt2 = 0; mt2 < 2; mt2++) {
        int grow0 = bm + mrow0 + mt2 * 16 + (lane >> 2);
        int b0 = grow0 >> 12;
        int s0 = grow0 & (SS - 1);
        #pragma unroll
        for (int nt = 0; nt < 8; nt++) {
            int gcol = bn + ncol0 + nt * 8 + 2 * (lane & 3);
            int head = gcol >> 6;
            int d    = gcol & 63;
            float2 bsv = *(const float2*)(bias + gcol);
            size_t idx = ((size_t)(b0 * NH + head) * SS + s0) * HD + d;
            float v0 = (acc[mt2][nt][0] + bsv.x) * scale;
            float v1 = (acc[mt2][nt][1] + bsv.y) * scale;
            float v2 = (acc[mt2][nt][2] + bsv.x) * scale;
            float v3 = (acc[mt2][nt][3] + bsv.y) * scale;
            uint32_t h01 = cvt_h2(v1, v0);
            uint32_t l01 = cvt_h2(v1 - h2_hi(h01), v0 - h2_lo(h01));
            uint32_t h23 = cvt_h2(v3, v2);
            uint32_t l23 = cvt_h2(v3 - h2_hi(h23), v2 - h2_lo(h23));
            *(uint32_t*)(dh + idx) = h01;
            *(uint32_t*)(dl + idx) = l01;
            *(uint32_t*)(dh + idx + (size_t)8 * HD) = h23;
            *(uint32_t*)(dl + idx + (size_t)8 * HD) = l23;
        }
    }
}

// ---------------------------------------------------------------------------
// Banded attention on tensor cores: 128-q tile, double-buffered K/V tiles,
// fp16 hi/lo 3-pass MMAs, FA2 register P conversion, poly exp.
// ---------------------------------------------------------------------------
#define ASTR 72
#define STAGE_BF (4 * 64 * ASTR)
#define A_SMEM   (2 * STAGE_BF * 2)

__global__ __launch_bounds__(256, 2) void attn_mma(
    const __half* __restrict__ qhi, const __half* __restrict__ qlo,
    const __half* __restrict__ khi, const __half* __restrict__ klo,
    const __half* __restrict__ vthi, const __half* __restrict__ vtlo,
    const float* __restrict__ fmask, const unsigned char* __restrict__ imask,
    float* __restrict__ out)
{
    extern __shared__ __half asmem[];
    __shared__ float fmk[2][64];
    const uint32_t smb = smem_u32(asmem);

    const int tid  = threadIdx.x;
    const int w    = tid >> 5;
    const int lane = tid & 31;
    const int bh   = blockIdx.y;
    const int b    = bh / NH;
    const int hh   = bh % NH;
    const int q0   = blockIdx.x * 128;

    const int lm  = lane >> 3;
    const int lr8 = lane & 7;
    const int a_row_off = (lm & 1) * 8 + lr8;
    const int a_col_off = (lm >> 1) * 8;
    const int b_row_off = (lm >> 1) * 8 + lr8;
    const int b_col_off = (lm & 1) * 8;
    const int gid = lane >> 2;
    const int tig = lane & 3;

    // ---- stage Q (hi rows 0-127, lo rows 128-255) ----
    #pragma unroll
    for (int it = 0; it < 8; it++) {
        int c = it * 256 + tid;
        int hilo = c >> 10;
        int r    = (c >> 3) & 127;
        int col  = c & 7;
        const __half* src = (hilo ? qlo : qhi)
            + ((size_t)bh * SS + q0 + r) * HD + col * 8;
        cpa16(smb + (uint32_t)(hilo * 128 * ASTR + r * ASTR + col * 8) * 2, src);
    }
    CPA_COMMIT();
    CPA_WAIT(0);
    __syncthreads();

    uint32_t qfh[16], qfl[16];
    #pragma unroll
    for (int kb = 0; kb < 4; kb++) {
        uint32_t off = (uint32_t)((w * 16 + a_row_off) * ASTR
                                  + kb * 16 + a_col_off) * 2;
        LDSM4(qfh[kb*4+0], qfh[kb*4+1], qfh[kb*4+2], qfh[kb*4+3], smb + off);
        LDSM4(qfl[kb*4+0], qfl[kb*4+1], qfl[kb*4+2], qfl[kb*4+3],
              smb + (uint32_t)(128 * ASTR) * 2 + off);
    }
    __syncthreads();

    float oacc[8][4];
    #pragma unroll
    for (int j = 0; j < 8; j++)
        #pragma unroll
        for (int u = 0; u < 4; u++) oacc[j][u] = 0.f;
    float rsum0 = 0.f, rsum1 = 0.f;

    const int row_lo = q0 + w * 16 + gid;
    const int row_hi = row_lo + 8;

    auto issue_tile = [&](int t, int st) {
        const int kstart = q0 - WIN + t * 64;
        #pragma unroll
        for (int it = 0; it < 8; it++) {
            int c    = it * 256 + tid;
            int tile = c >> 9;
            int r    = (c >> 3) & 63;
            int col  = c & 7;
            const __half* src;
            if (tile == 0)
                src = khi + ((size_t)bh * SS + kstart + r) * HD + col * 8;
            else if (tile == 1)
                src = klo + ((size_t)bh * SS + kstart + r) * HD + col * 8;
            else if (tile == 2)
                src = vthi + ((size_t)bh * HD + r) * SS + kstart + col * 8;
            else
                src = vtlo + ((size_t)bh * HD + r) * SS + kstart + col * 8;
            cpa16(smb + (uint32_t)(st * STAGE_BF + tile * 64 * ASTR
                                   + r * ASTR + col * 8) * 2, src);
        }
        CPA_COMMIT();
        if (tid < 64) {
            float mv = fmask[b * SS + kstart + tid];
            fmk[st][tid] = (mv != 0.f) ? -1e30f : 0.f;
        }
    };

    const int tfirst = (q0 < WIN) ? ((WIN - q0) >> 6) : 0;
    int tlast = (SS - 64 + WIN - q0) >> 6;
    if (tlast > 9) tlast = 9;

    issue_tile(tfirst, 0);
    int st = 0;
    for (int t = tfirst; t <= tlast; t++, st ^= 1) {
        if (t < tlast) {
            issue_tile(t + 1, st ^ 1);
            CPA_WAIT(1);
        } else {
            CPA_WAIT(0);
        }
        __syncthreads();

        const int kstart = q0 - WIN + t * 64;
        const bool edge = (t < 2) || (t > 7);
        const uint32_t sb = smb + (uint32_t)(st * STAGE_BF) * 2;

        // ---- S = Q K^T (3-pass hi/lo) ----
        float s[8][4];
        #pragma unroll
        for (int j = 0; j < 8; j++)
            #pragma unroll
            for (int u = 0; u < 4; u++) s[j][u] = 0.f;
        #pragma unroll
        for (int kb = 0; kb < 4; kb++) {
            #pragma unroll
            for (int ng = 0; ng < 4; ng++) {
                uint32_t off = (uint32_t)((ng * 16 + b_row_off) * ASTR
                                          + kb * 16 + b_col_off) * 2;
                uint32_t kh0, kh1, kh2, kh3, kl0, kl1, kl2, kl3;
                LDSM4(kh0, kh1, kh2, kh3, sb + off);
                LDSM4(kl0, kl1, kl2, kl3,
                      sb + (uint32_t)(64 * ASTR) * 2 + off);
                MMA16816(s[2*ng],   &qfh[kb*4], kh0, kh1);
                MMA16816(s[2*ng],   &qfh[kb*4], kl0, kl1);
                MMA16816(s[2*ng],   &qfl[kb*4], kh0, kh1);
                MMA16816(s[2*ng+1], &qfh[kb*4], kh2, kh3);
                MMA16816(s[2*ng+1], &qfh[kb*4], kl2, kl3);
                MMA16816(s[2*ng+1], &qfl[kb*4], kh2, kh3);
            }
        }

        // ---- exp + window mask + row sums ----
        float rl = 0.f, rh = 0.f;
        #pragma unroll
        for (int nf = 0; nf < 8; nf++) {
            int key0 = kstart + nf * 8 + 2 * tig;
            float fm0 = fmk[st][nf * 8 + 2 * tig];
            float fm1 = fmk[st][nf * 8 + 2 * tig + 1];
            float p0 = expfast(s[nf][0] + fm0);
            float p1 = expfast(s[nf][1] + fm1);
            float p2 = expfast(s[nf][2] + fm0);
            float p3 = expfast(s[nf][3] + fm1);
            if (edge) {
                if (abs(key0     - row_lo) > WIN) p0 = 0.f;
                if (abs(key0 + 1 - row_lo) > WIN) p1 = 0.f;
                if (abs(key0     - row_hi) > WIN) p2 = 0.f;
                if (abs(key0 + 1 - row_hi) > WIN) p3 = 0.f;
            }
            s[nf][0] = p0; s[nf][1] = p1; s[nf][2] = p2; s[nf][3] = p3;
            rl += p0 + p1;
            rh += p2 + p3;
        }
        rl += __shfl_xor_sync(0xffffffffu, rl, 1);
        rl += __shfl_xor_sync(0xffffffffu, rl, 2);
        rh += __shfl_xor_sync(0xffffffffu, rh, 1);
        rh += __shfl_xor_sync(0xffffffffu, rh, 2);
        rsum0 += rl;
        rsum1 += rh;

        // ---- P -> fp16 hi/lo A-frags (register-only) ----
        uint32_t aph[4][4], apl[4][4];
        #pragma unroll
        for (int j = 0; j < 4; j++) {
            uint32_t h;
            h = cvt_h2(s[2*j][1], s[2*j][0]);
            aph[j][0] = h;
            apl[j][0] = cvt_h2(s[2*j][1] - h2_hi(h), s[2*j][0] - h2_lo(h));
            h = cvt_h2(s[2*j][3], s[2*j][2]);
            aph[j][1] = h;
            apl[j][1] = cvt_h2(s[2*j][3] - h2_hi(h), s[2*j][2] - h2_lo(h));
            h = cvt_h2(s[2*j+1][1], s[2*j+1][0]);
            aph[j][2] = h;
            apl[j][2] = cvt_h2(s[2*j+1][1] - h2_hi(h), s[2*j+1][0] - h2_lo(h));
            h = cvt_h2(s[2*j+1][3], s[2*j+1][2]);
            aph[j][3] = h;
            apl[j][3] = cvt_h2(s[2*j+1][3] - h2_hi(h), s[2*j+1][2] - h2_lo(h));
        }

        // ---- O += P V (3-pass hi/lo) ----
        #pragma unroll
        for (int j = 0; j < 4; j++) {
            #pragma unroll
            for (int nb = 0; nb < 4; nb++) {
                uint32_t off = (uint32_t)((nb * 16 + b_row_off) * ASTR
                                          + j * 16 + b_col_off) * 2;
                uint32_t vh0, vh1, vh2, vh3, vl0, vl1, vl2, vl3;
                LDSM4(vh0, vh1, vh2, vh3,
                      sb + (uint32_t)(2 * 64 * ASTR) * 2 + off);
                LDSM4(vl0, vl1, vl2, vl3,
                      sb + (uint32_t)(3 * 64 * ASTR) * 2 + off);
                MMA16816(oacc[2*nb],   aph[j], vh0, vh1);
                MMA16816(oacc[2*nb],   aph[j], vl0, vl1);
                MMA16816(oacc[2*nb],   apl[j], vh0, vh1);
                MMA16816(oacc[2*nb+1], aph[j], vh2, vh3);
                MMA16816(oacc[2*nb+1], aph[j], vl2, vl3);
                MMA16816(oacc[2*nb+1], apl[j], vh2, vh3);
            }
        }
        __syncthreads();
    }

    // ---- epilogue ----
    float inv0 = 1.f / rsum0;
    float inv1 = 1.f / rsum1;
    if (imask[b * SS + row_lo]) inv0 = 0.f;
    if (imask[b * SS + row_hi]) inv1 = 0.f;
    float* o0 = out + ((size_t)b * SS + row_lo) * DD + hh * HD + 2 * tig;
    float* o1 = out + ((size_t)b * SS + row_hi) * DD + hh * HD + 2 * tig;
    #pragma unroll
    for (int nf = 0; nf < 8; nf++) {
        float2 w0 = make_float2(oacc[nf][0] * inv0, oacc[nf][1] * inv0);
        float2 w1 = make_float2(oacc[nf][2] * inv1, oacc[nf][3] * inv1);
        *(float2*)(o0 + nf * 8) = w0;
        *(float2*)(o1 + nf * 8) = w1;
    }
}

// ---------------------------------------------------------------------------
extern "C" void kernel_launch(void* const* d_in, const int* in_sizes, int n_in,
                              void* d_out, int out_size)
{
    const float* hidden = (const float*)d_in[0];
    const float* amask  = (const float*)d_in[1];
    const unsigned char* imask = (const unsigned char*)d_in[2];
    const float* Wq = (const float*)d_in[3];
    const float* bq = (const float*)d_in[4];
    const float* Wk = (const float*)d_in[5];
    const float* bk = (const float*)d_in[6];
    const float* Wv = (const float*)d_in[7];
    const float* bv = (const float*)d_in[8];
    float* out = (float*)d_out;

    __half *pa, *pwhi, *pwlo;
    __half *pqh, *pql, *pkh, *pkl, *pvh, *pvl, *pvth, *pvtl;
    cudaGetSymbolAddress((void**)&pa, g_a);
    cudaGetSymbolAddress((void**)&pwhi, g_wthi);
    cudaGetSymbolAddress((void**)&pwlo, g_wtlo);
    cudaGetSymbolAddress((void**)&pqh, g_qhi);
    cudaGetSymbolAddress((void**)&pql, g_qlo);
    cudaGetSymbolAddress((void**)&pkh, g_khi);
    cudaGetSymbolAddress((void**)&pkl, g_klo);
    cudaGetSymbolAddress((void**)&pvh, g_vhi);
    cudaGetSymbolAddress((void**)&pvl, g_vlo);
    cudaGetSymbolAddress((void**)&pvth, g_vthi);
    cudaGetSymbolAddress((void**)&pvtl, g_vtlo);

    cudaFuncSetAttribute(qkv_gemm_mma,
                         cudaFuncAttributeMaxDynamicSharedMemorySize, G_SMEM);
    cudaFuncSetAttribute(attn_mma,
                         cudaFuncAttributeMaxDynamicSharedMemorySize, A_SMEM);

    // prep: fp16 conversions / splits
    asplit<<<592, 256>>>((const float4*)hidden, (__half2*)pa,
                         BB * SS * DD / 4);
    dim3 wb(32, 8), wg(DD / 32, DD / 32, 3);
    wsplit3<<<wg, wb>>>(Wq, Wk, Wv, pwhi, pwlo);

    // tensor-core QKV GEMMs (2-pass fp16) -> Q/K/V hi/lo
    dim3 gg(DD / 128, (BB * SS) / 128, 3);
    qkv_gemm_mma<<<gg, 256, G_SMEM>>>(pa, pwhi, pwlo,
                                      bq, bk, bv,
                                      pqh, pql, pkh, pkl, pvh, pvl);

    // V transpose for PV mma B-operand
    dim3 vg(SS / 64, BH, 2);
    vtrans<<<vg, 256>>>(pvh, pvl, pvth, pvtl);

    // tensor-core banded attention (double-buffered)
    dim3 agrid(SS / 128, BH);
    attn_mma<<<agrid, 256, A_SMEM>>>(pqh, pql, pkh, pkl, pvth, pvtl,
                                     amask, imask, out);
}

// round 16
// speedup vs baseline: 1.5091x; 1.1815x over previous
#include <cuda_runtime.h>
#include <cuda_fp16.h>
#include <math.h>
#include <stdint.h>

#define BB 2
#define SS 4096
#define DD 768
#define NH 12
#define HD 64
#define WIN 256
#define BH (BB*NH)

// ---------------------------------------------------------------------------
// scratch (fp16: A, Q, K single precision-level; W hi/lo; V hi/lo for PV)
// ---------------------------------------------------------------------------
__device__ __half g_a[BB*SS*DD];
__device__ __half g_wthi[3][DD*DD];
__device__ __half g_wtlo[3][DD*DD];
__device__ __half g_q[BH*SS*HD];
__device__ __half g_k[BH*SS*HD];
__device__ __half g_vhi[BH*SS*HD], g_vlo[BH*SS*HD];
__device__ __half g_vthi[BH*HD*SS], g_vtlo[BH*HD*SS];

// ---------------------------------------------------------------------------
// helpers
// ---------------------------------------------------------------------------
__device__ __forceinline__ uint32_t smem_u32(const void* p) {
    uint32_t a;
    asm("{ .reg .u64 t; cvta.to.shared.u64 t, %1; cvt.u32.u64 %0, t; }"
        : "=r"(a) : "l"(p));
    return a;
}
#define LDSM4(r0,r1,r2,r3,addr) \
    asm volatile("ldmatrix.sync.aligned.m8n8.x4.shared.b16 {%0,%1,%2,%3}, [%4];" \
        : "=r"(r0),"=r"(r1),"=r"(r2),"=r"(r3) : "r"(addr))
#define MMA16816(c, a, b0, b1) \
    asm volatile("mma.sync.aligned.m16n8k16.row.col.f32.f16.f16.f32 " \
        "{%0,%1,%2,%3}, {%4,%5,%6,%7}, {%8,%9}, {%0,%1,%2,%3};" \
        : "+f"((c)[0]),"+f"((c)[1]),"+f"((c)[2]),"+f"((c)[3]) \
        : "r"((a)[0]),"r"((a)[1]),"r"((a)[2]),"r"((a)[3]),"r"(b0),"r"(b1))
__device__ __forceinline__ void cpa16(uint32_t dst, const void* src) {
    asm volatile("cp.async.cg.shared.global [%0], [%1], 16;"
                 :: "r"(dst), "l"(src));
}
#define CPA_COMMIT() asm volatile("cp.async.commit_group;" ::: "memory")
#define CPA_WAIT(n)  asm volatile("cp.async.wait_group %0;" :: "n"(n) : "memory")

// pack two f32 -> f16x2 (first operand -> high half)
__device__ __forceinline__ uint32_t cvt_h2(float hi, float lo) {
    uint32_t r;
    asm("cvt.rn.f16x2.f32 %0, %1, %2;" : "=r"(r) : "f"(hi), "f"(lo));
    return r;
}
__device__ __forceinline__ float h2_lo(uint32_t u) {
    float r;
    asm("{.reg .b16 l, h; mov.b32 {l, h}, %1; cvt.f32.f16 %0, l;}"
        : "=f"(r) : "r"(u));
    return r;
}
__device__ __forceinline__ float h2_hi(uint32_t u) {
    float r;
    asm("{.reg .b16 l, h; mov.b32 {l, h}, %1; cvt.f32.f16 %0, h;}"
        : "=f"(r) : "r"(u));
    return r;
}

__device__ __forceinline__ float expfast(float x) {
    float z = x * 1.4426950408889634f;
    z = fmaxf(z, -126.0f);
    float t = z + 12582912.0f;
    int   ni = __float_as_int(t) - 0x4B400000;
    float n = t - 12582912.0f;
    float r = z - n;
    float p = fmaf(1.5403530393381609e-4f, r, 1.3333558146428443e-3f);
    p = fmaf(p, r, 9.6181291076284772e-3f);
    p = fmaf(p, r, 5.5504108664821580e-2f);
    p = fmaf(p, r, 2.4022650695910072e-1f);
    p = fmaf(p, r, 6.9314718055994531e-1f);
    p = fmaf(p, r, 1.0f);
    return p * __int_as_float((ni + 127) << 23);
}

// ---------------------------------------------------------------------------
// prep kernels
// ---------------------------------------------------------------------------
__global__ __launch_bounds__(256) void asplit(const float4* __restrict__ in,
                                              __half2* __restrict__ hi, int n4)
{
    int i = blockIdx.x * blockDim.x + threadIdx.x;
    int stride = gridDim.x * blockDim.x;
    for (; i < n4; i += stride) {
        float4 f = in[i];
        hi[2*i]   = __floats2half2_rn(f.x, f.y);
        hi[2*i+1] = __floats2half2_rn(f.z, f.w);
    }
}

__global__ __launch_bounds__(256) void wsplit3(
    const float* __restrict__ Wq, const float* __restrict__ Wk,
    const float* __restrict__ Wv,
    __half* __restrict__ hi_all, __half* __restrict__ lo_all)
{
    __shared__ float t[32][33];
    const int z = blockIdx.z;
    const float* __restrict__ W = (z == 0) ? Wq : ((z == 1) ? Wk : Wv);
    __half* hi = hi_all + (size_t)z * DD * DD;
    __half* lo = lo_all + (size_t)z * DD * DD;
    int tx = threadIdx.x, ty = threadIdx.y;
    int bx = blockIdx.x * 32, by = blockIdx.y * 32;
    #pragma unroll
    for (int i = 0; i < 4; i++)
        t[ty + i*8][tx] = W[(size_t)(by + ty + i*8) * DD + bx + tx];
    __syncthreads();
    #pragma unroll
    for (int i = 0; i < 4; i++) {
        float x = t[tx][ty + i*8];
        __half h = __float2half_rn(x);
        hi[(size_t)(bx + ty + i*8) * DD + by + tx] = h;
        lo[(size_t)(bx + ty + i*8) * DD + by + tx] =
            __float2half_rn(x - __half2float(h));
    }
}

// transpose V [bh][S][64] -> VT [bh][64][S]; z selects hi/lo
__global__ __launch_bounds__(256) void vtrans(
    const __half* __restrict__ vhi, const __half* __restrict__ vlo,
    __half* __restrict__ vthi, __half* __restrict__ vtlo)
{
    __shared__ unsigned short sm[64][65];
    const int s0 = blockIdx.x * 64;
    const int bh = blockIdx.y;
    const __half* src = (blockIdx.z ? vlo : vhi) + (size_t)bh * SS * HD;
    __half* dst       = (blockIdx.z ? vtlo : vthi) + (size_t)bh * HD * SS;
    const int tid = threadIdx.x;
    const int r = tid >> 2, c0 = (tid & 3) * 16;
    {
        uint4 a = *(const uint4*)(src + (size_t)(s0 + r) * HD + c0);
        uint4 b = *(const uint4*)(src + (size_t)(s0 + r) * HD + c0 + 8);
        const unsigned short* pa = (const unsigned short*)&a;
        const unsigned short* pb = (const unsigned short*)&b;
        #pragma unroll
        for (int i = 0; i < 8; i++) { sm[r][c0+i] = pa[i]; sm[r][c0+8+i] = pb[i]; }
    }
    __syncthreads();
    {
        unsigned short w[16];
        #pragma unroll
        for (int i = 0; i < 16; i++) w[i] = sm[c0 + i][r];
        *(uint4*)(dst + (size_t)r * SS + s0 + c0)     = *(uint4*)&w[0];
        *(uint4*)(dst + (size_t)r * SS + s0 + c0 + 8) = *(uint4*)&w[8];
    }
}

// ---------------------------------------------------------------------------
// QKV GEMM on tensor cores, fp16 2-pass: D = A*Whi + A*Wlo.
// z=0/1 -> Q/K (fp16, single); z=2 -> V hi/lo (for PV accuracy).
// ---------------------------------------------------------------------------
#define TSTR    40
#define TILE_E  (128 * TSTR)
#define STAGE_E (3 * TILE_E)
#define G_SMEM  (2 * STAGE_E * 2)
#define NCHUNK  (DD / 32)

__global__ __launch_bounds__(256) void qkv_gemm_mma(
    const __half* __restrict__ A,
    const __half* __restrict__ Whi_all, const __half* __restrict__ Wlo_all,
    const float* __restrict__ bq, const float* __restrict__ bk,
    const float* __restrict__ bv,
    __half* __restrict__ q, __half* __restrict__ k,
    __half* __restrict__ vh, __half* __restrict__ vl)
{
    extern __shared__ __half gsm[];
    const uint32_t smb = smem_u32(gsm);

    const int z = blockIdx.z;
    const __half* __restrict__ Whi = Whi_all + (size_t)z * DD * DD;
    const __half* __restrict__ Wlo = Wlo_all + (size_t)z * DD * DD;
    const float* __restrict__ bias = (z == 0) ? bq : ((z == 1) ? bk : bv);
    __half* dh = (z == 0) ? q : ((z == 1) ? k : vh);
    const float scale = (z == 0) ? 0.125f : 1.0f;

    const int tid  = threadIdx.x;
    const int wid  = tid >> 5;
    const int lane = tid & 31;
    const int bm   = blockIdx.y * 128;
    const int bn   = blockIdx.x * 128;
    const int mrow0 = (wid & 3) * 32;
    const int ncol0 = (wid >> 2) * 64;
    const int lr0 = tid >> 2;
    const int lg  = tid & 3;

    float acc[2][8][4];
    #pragma unroll
    for (int i = 0; i < 2; i++)
        #pragma unroll
        for (int j = 0; j < 8; j++)
            #pragma unroll
            for (int u = 0; u < 4; u++) acc[i][j][u] = 0.f;

    const int lm  = lane >> 3;
    const int lr8 = lane & 7;
    const int a_row_off = (lm & 1) * 8 + lr8;
    const int a_col_off = (lm >> 1) * 8;
    const int b_row_off = (lm >> 1) * 8 + lr8;
    const int b_col_off = (lm & 1) * 8;

    auto load_chunk = [&](int c, int s) {
        const int k0 = c * 32;
        const uint32_t sbase = smb + (uint32_t)(s * STAGE_E) * 2;
        const __half* srcs[3] = {
            A   + (size_t)bm * DD + k0,
            Whi + (size_t)bn * DD + k0,
            Wlo + (size_t)bn * DD + k0 };
        #pragma unroll
        for (int t3 = 0; t3 < 3; t3++) {
            #pragma unroll
            for (int it = 0; it < 2; it++) {
                int r = lr0 + it * 64;
                cpa16(sbase + (uint32_t)(t3 * TILE_E + r * TSTR + lg * 8) * 2,
                      srcs[t3] + (size_t)r * DD + lg * 8);
            }
        }
        CPA_COMMIT();
    };

    load_chunk(0, 0);
    CPA_WAIT(0);
    __syncthreads();

    for (int c = 0; c < NCHUNK; c++) {
        if (c + 1 < NCHUNK) {
            load_chunk(c + 1, (c + 1) & 1);
            CPA_WAIT(1);
        } else {
            CPA_WAIT(0);
        }
        __syncthreads();

        const uint32_t sbase = smb + (uint32_t)((c & 1) * STAGE_E) * 2;
        const uint32_t baseA   = sbase;
        const uint32_t baseWhi = sbase + (uint32_t)TILE_E * 2;
        const uint32_t baseWlo = sbase + (uint32_t)(2 * TILE_E) * 2;

        #pragma unroll
        for (int kk = 0; kk < 32; kk += 16) {
            uint32_t ah[2][4];
            #pragma unroll
            for (int mt2 = 0; mt2 < 2; mt2++) {
                uint32_t off = (uint32_t)((mrow0 + mt2 * 16 + a_row_off) * TSTR
                                          + kk + a_col_off) * 2;
                LDSM4(ah[mt2][0], ah[mt2][1], ah[mt2][2], ah[mt2][3],
                      baseA + off);
            }
            uint32_t bh[16], bl[16];
            #pragma unroll
            for (int ng = 0; ng < 4; ng++) {
                uint32_t off = (uint32_t)((ncol0 + ng * 16 + b_row_off) * TSTR
                                          + kk + b_col_off) * 2;
                LDSM4(bh[ng*4+0], bh[ng*4+1], bh[ng*4+2], bh[ng*4+3],
                      baseWhi + off);
                LDSM4(bl[ng*4+0], bl[ng*4+1], bl[ng*4+2], bl[ng*4+3],
                      baseWlo + off);
            }
            #pragma unroll
            for (int mt2 = 0; mt2 < 2; mt2++) {
                #pragma unroll
                for (int nt = 0; nt < 8; nt++) {
                    int bi = (nt >> 1) * 4 + (nt & 1) * 2;
                    MMA16816(acc[mt2][nt], ah[mt2], bh[bi], bh[bi+1]);
                    MMA16816(acc[mt2][nt], ah[mt2], bl[bi], bl[bi+1]);
                }
            }
        }
        __syncthreads();
    }

    // epilogue: (acc+bias)*scale -> fp16 at [b,h,s,d]; V also writes lo
    #pragma unroll
    for (int mt2 = 0; mt2 < 2; mt2++) {
        int grow0 = bm + mrow0 + mt2 * 16 + (lane >> 2);
        int b0 = grow0 >> 12;
        int s0 = grow0 & (SS - 1);
        #pragma unroll
        for (int nt = 0; nt < 8; nt++) {
            int gcol = bn + ncol0 + nt * 8 + 2 * (lane & 3);
            int head = gcol >> 6;
            int d    = gcol & 63;
            float2 bsv = *(const float2*)(bias + gcol);
            size_t idx = ((size_t)(b0 * NH + head) * SS + s0) * HD + d;
            float v0 = (acc[mt2][nt][0] + bsv.x) * scale;
            float v1 = (acc[mt2][nt][1] + bsv.y) * scale;
            float v2 = (acc[mt2][nt][2] + bsv.x) * scale;
            float v3 = (acc[mt2][nt][3] + bsv.y) * scale;
            uint32_t h01 = cvt_h2(v1, v0);
            uint32_t h23 = cvt_h2(v3, v2);
            *(uint32_t*)(dh + idx) = h01;
            *(uint32_t*)(dh + idx + (size_t)8 * HD) = h23;
            if (z == 2) {
                uint32_t l01 = cvt_h2(v1 - h2_hi(h01), v0 - h2_lo(h01));
                uint32_t l23 = cvt_h2(v3 - h2_hi(h23), v2 - h2_lo(h23));
                *(uint32_t*)(vl + idx) = l01;
                *(uint32_t*)(vl + idx + (size_t)8 * HD) = l23;
            }
        }
    }
}

// ---------------------------------------------------------------------------
// Banded attention: 128-q tile, double-buffered 3-tile stages (Khi/VThi/VTlo),
// S = pure-fp16 QK^T (1-pass), PV = Phi*(Vhi+Vlo) (2-pass), poly exp.
// ---------------------------------------------------------------------------
#define ASTR 72
#define STAGE_HF (3 * 64 * ASTR)
#define A_SMEM   (2 * STAGE_HF * 2)

__global__ __launch_bounds__(256, 2) void attn_mma(
    const __half* __restrict__ qg, const __half* __restrict__ kg,
    const __half* __restrict__ vthi, const __half* __restrict__ vtlo,
    const float* __restrict__ fmask, const unsigned char* __restrict__ imask,
    float* __restrict__ out)
{
    extern __shared__ __half asmem[];
    __shared__ float fmk[2][64];
    const uint32_t smb = smem_u32(asmem);

    const int tid  = threadIdx.x;
    const int w    = tid >> 5;
    const int lane = tid & 31;
    const int bh   = blockIdx.y;
    const int b    = bh / NH;
    const int hh   = bh % NH;
    const int q0   = blockIdx.x * 128;

    const int lm  = lane >> 3;
    const int lr8 = lane & 7;
    const int a_row_off = (lm & 1) * 8 + lr8;
    const int a_col_off = (lm >> 1) * 8;
    const int b_row_off = (lm >> 1) * 8 + lr8;
    const int b_col_off = (lm & 1) * 8;
    const int gid = lane >> 2;
    const int tig = lane & 3;

    // ---- stage Q (128 rows, fp16) ----
    #pragma unroll
    for (int it = 0; it < 4; it++) {
        int c = it * 256 + tid;
        int r    = c >> 3;
        int col  = c & 7;
        const __half* src = qg + ((size_t)bh * SS + q0 + r) * HD + col * 8;
        cpa16(smb + (uint32_t)(r * ASTR + col * 8) * 2, src);
    }
    CPA_COMMIT();
    CPA_WAIT(0);
    __syncthreads();

    uint32_t qf[16];
    #pragma unroll
    for (int kb = 0; kb < 4; kb++) {
        uint32_t off = (uint32_t)((w * 16 + a_row_off) * ASTR
                                  + kb * 16 + a_col_off) * 2;
        LDSM4(qf[kb*4+0], qf[kb*4+1], qf[kb*4+2], qf[kb*4+3], smb + off);
    }
    __syncthreads();       // Q region reused as stage 0

    float oacc[8][4];
    #pragma unroll
    for (int j = 0; j < 8; j++)
        #pragma unroll
        for (int u = 0; u < 4; u++) oacc[j][u] = 0.f;
    float rsum0 = 0.f, rsum1 = 0.f;

    const int row_lo = q0 + w * 16 + gid;
    const int row_hi = row_lo + 8;

    auto issue_tile = [&](int t, int st) {
        const int kstart = q0 - WIN + t * 64;
        #pragma unroll
        for (int it = 0; it < 6; it++) {
            int c    = it * 256 + tid;
            int tile = c >> 9;
            int r    = (c >> 3) & 63;
            int col  = c & 7;
            const __half* src;
            if (tile == 0)
                src = kg + ((size_t)bh * SS + kstart + r) * HD + col * 8;
            else if (tile == 1)
                src = vthi + ((size_t)bh * HD + r) * SS + kstart + col * 8;
            else
                src = vtlo + ((size_t)bh * HD + r) * SS + kstart + col * 8;
            cpa16(smb + (uint32_t)(st * STAGE_HF + tile * 64 * ASTR
                                   + r * ASTR + col * 8) * 2, src);
        }
        CPA_COMMIT();
        if (tid < 64) {
            float mv = fmask[b * SS + kstart + tid];
            fmk[st][tid] = (mv != 0.f) ? -1e30f : 0.f;
        }
    };

    const int tfirst = (q0 < WIN) ? ((WIN - q0) >> 6) : 0;
    int tlast = (SS - 64 + WIN - q0) >> 6;
    if (tlast > 9) tlast = 9;

    issue_tile(tfirst, 0);
    int st = 0;
    for (int t = tfirst; t <= tlast; t++, st ^= 1) {
        if (t < tlast) {
            issue_tile(t + 1, st ^ 1);
            CPA_WAIT(1);
        } else {
            CPA_WAIT(0);
        }
        __syncthreads();

        const int kstart = q0 - WIN + t * 64;
        const bool edge = (t < 2) || (t > 7);
        const uint32_t sb = smb + (uint32_t)(st * STAGE_HF) * 2;

        // ---- S = Q K^T (pure fp16, 1-pass) ----
        float s[8][4];
        #pragma unroll
        for (int j = 0; j < 8; j++)
            #pragma unroll
            for (int u = 0; u < 4; u++) s[j][u] = 0.f;
        #pragma unroll
        for (int kb = 0; kb < 4; kb++) {
            #pragma unroll
            for (int ng = 0; ng < 4; ng++) {
                uint32_t off = (uint32_t)((ng * 16 + b_row_off) * ASTR
                                          + kb * 16 + b_col_off) * 2;
                uint32_t k0, k1, k2, k3;
                LDSM4(k0, k1, k2, k3, sb + off);
                MMA16816(s[2*ng],   &qf[kb*4], k0, k1);
                MMA16816(s[2*ng+1], &qf[kb*4], k2, k3);
            }
        }

        // ---- exp + window mask + row sums ----
        float rl = 0.f, rh = 0.f;
        #pragma unroll
        for (int nf = 0; nf < 8; nf++) {
            int key0 = kstart + nf * 8 + 2 * tig;
            float fm0 = fmk[st][nf * 8 + 2 * tig];
            float fm1 = fmk[st][nf * 8 + 2 * tig + 1];
            float p0 = expfast(s[nf][0] + fm0);
            float p1 = expfast(s[nf][1] + fm1);
            float p2 = expfast(s[nf][2] + fm0);
            float p3 = expfast(s[nf][3] + fm1);
            if (edge) {
                if (abs(key0     - row_lo) > WIN) p0 = 0.f;
                if (abs(key0 + 1 - row_lo) > WIN) p1 = 0.f;
                if (abs(key0     - row_hi) > WIN) p2 = 0.f;
                if (abs(key0 + 1 - row_hi) > WIN) p3 = 0.f;
            }
            s[nf][0] = p0; s[nf][1] = p1; s[nf][2] = p2; s[nf][3] = p3;
            rl += p0 + p1;
            rh += p2 + p3;
        }
        rl += __shfl_xor_sync(0xffffffffu, rl, 1);
        rl += __shfl_xor_sync(0xffffffffu, rl, 2);
        rh += __shfl_xor_sync(0xffffffffu, rh, 1);
        rh += __shfl_xor_sync(0xffffffffu, rh, 2);
        rsum0 += rl;
        rsum1 += rh;

        // ---- P -> fp16 A-frags (hi only, register-only) ----
        uint32_t aph[4][4];
        #pragma unroll
        for (int j = 0; j < 4; j++) {
            aph[j][0] = cvt_h2(s[2*j][1],   s[2*j][0]);
            aph[j][1] = cvt_h2(s[2*j][3],   s[2*j][2]);
            aph[j][2] = cvt_h2(s[2*j+1][1], s[2*j+1][0]);
            aph[j][3] = cvt_h2(s[2*j+1][3], s[2*j+1][2]);
        }

        // ---- O += P V (2-pass: V hi + V lo) ----
        #pragma unroll
        for (int j = 0; j < 4; j++) {
            #pragma unroll
            for (int nb = 0; nb < 4; nb++) {
                uint32_t off = (uint32_t)((nb * 16 + b_row_off) * ASTR
                                          + j * 16 + b_col_off) * 2;
                uint32_t vh0, vh1, vh2, vh3, vl0, vl1, vl2, vl3;
                LDSM4(vh0, vh1, vh2, vh3,
                      sb + (uint32_t)(64 * ASTR) * 2 + off);
                LDSM4(vl0, vl1, vl2, vl3,
                      sb + (uint32_t)(2 * 64 * ASTR) * 2 + off);
                MMA16816(oacc[2*nb],   aph[j], vh0, vh1);
                MMA16816(oacc[2*nb],   aph[j], vl0, vl1);
                MMA16816(oacc[2*nb+1], aph[j], vh2, vh3);
                MMA16816(oacc[2*nb+1], aph[j], vl2, vl3);
            }
        }
        __syncthreads();
    }

    // ---- epilogue ----
    float inv0 = 1.f / rsum0;
    float inv1 = 1.f / rsum1;
    if (imask[b * SS + row_lo]) inv0 = 0.f;
    if (imask[b * SS + row_hi]) inv1 = 0.f;
    float* o0 = out + ((size_t)b * SS + row_lo) * DD + hh * HD + 2 * tig;
    float* o1 = out + ((size_t)b * SS + row_hi) * DD + hh * HD + 2 * tig;
    #pragma unroll
    for (int nf = 0; nf < 8; nf++) {
        float2 w0 = make_float2(oacc[nf][0] * inv0, oacc[nf][1] * inv0);
        float2 w1 = make_float2(oacc[nf][2] * inv1, oacc[nf][3] * inv1);
        *(float2*)(o0 + nf * 8) = w0;
        *(float2*)(o1 + nf * 8) = w1;
    }
}

// ---------------------------------------------------------------------------
extern "C" void kernel_launch(void* const* d_in, const int* in_sizes, int n_in,
                              void* d_out, int out_size)
{
    const float* hidden = (const float*)d_in[0];
    const float* amask  = (const float*)d_in[1];
    const unsigned char* imask = (const unsigned char*)d_in[2];
    const float* Wq = (const float*)d_in[3];
    const float* bq = (const float*)d_in[4];
    const float* Wk = (const float*)d_in[5];
    const float* bk = (const float*)d_in[6];
    const float* Wv = (const float*)d_in[7];
    const float* bv = (const float*)d_in[8];
    float* out = (float*)d_out;

    __half *pa, *pwhi, *pwlo;
    __half *pq, *pk, *pvh, *pvl, *pvth, *pvtl;
    cudaGetSymbolAddress((void**)&pa, g_a);
    cudaGetSymbolAddress((void**)&pwhi, g_wthi);
    cudaGetSymbolAddress((void**)&pwlo, g_wtlo);
    cudaGetSymbolAddress((void**)&pq, g_q);
    cudaGetSymbolAddress((void**)&pk, g_k);
    cudaGetSymbolAddress((void**)&pvh, g_vhi);
    cudaGetSymbolAddress((void**)&pvl, g_vlo);
    cudaGetSymbolAddress((void**)&pvth, g_vthi);
    cudaGetSymbolAddress((void**)&pvtl, g_vtlo);

    cudaFuncSetAttribute(qkv_gemm_mma,
                         cudaFuncAttributeMaxDynamicSharedMemorySize, G_SMEM);
    cudaFuncSetAttribute(attn_mma,
                         cudaFuncAttributeMaxDynamicSharedMemorySize, A_SMEM);

    // prep: fp16 conversions / splits
    asplit<<<592, 256>>>((const float4*)hidden, (__half2*)pa,
                         BB * SS * DD / 4);
    dim3 wb(32, 8), wg(DD / 32, DD / 32, 3);
    wsplit3<<<wg, wb>>>(Wq, Wk, Wv, pwhi, pwlo);

    // tensor-core QKV GEMMs (2-pass fp16) -> Q, K fp16; V hi/lo
    dim3 gg(DD / 128, (BB * SS) / 128, 3);
    qkv_gemm_mma<<<gg, 256, G_SMEM>>>(pa, pwhi, pwlo,
                                      bq, bk, bv,
                                      pq, pk, pvh, pvl);

    // V transpose for PV mma B-operand
    dim3 vg(SS / 64, BH, 2);
    vtrans<<<vg, 256>>>(pvh, pvl, pvth, pvtl);

    // tensor-core banded attention (double-buffered, 3-tile stages)
    dim3 agrid(SS / 128, BH);
    attn_mma<<<agrid, 256, A_SMEM>>>(pq, pk, pvth, pvtl,
                                     amask, imask, out);
}